// round 14
// baseline (speedup 1.0000x reference)
#include <cuda_runtime.h>
#include <cuda_bf16.h>
#include <cstdint>
#include <math.h>

// ===========================================================================
// GCN2 on GB300: double-buffered mma.sync bf16 3-term-split GEMMs
// + CSR aggregation reordered per layer (layer1 input-side, layer2/3 output).
// R12: revert R11's 2-CTA/SM cap (it forced spills); keep early A-conversion
// (fp32 -> packed bf16 hi/lo at LDG time) with natural register allocation.
// ===========================================================================

#define NN 10000
#define CMAX 1024
#define EMAX 200000

__device__ float g_lin1[NN * CMAX];
__device__ float g_lin2[NN * CMAX];
__device__ float g_h   [NN * CMAX];
__device__ float g_y1  [NN * 512];
__device__ float g_y2  [NN * 512];
__device__ float g_dinv1[NN];
__device__ float g_dinv2[NN];
__device__ int   g_cnt1[NN];
__device__ int   g_cnt2[NN];
__device__ int   g_rp1[NN + 1];
__device__ int   g_rp2[NN + 1];
__device__ int   g_cur1[NN];
__device__ int   g_cur2[NN];
__device__ int   g_col1[EMAX];
__device__ int   g_col2[EMAX];
__device__ __nv_bfloat16 g_wth1[1024 * 1024];
__device__ __nv_bfloat16 g_wtl1[1024 * 1024];
__device__ __nv_bfloat16 g_wth2[1024 * 1024];
__device__ __nv_bfloat16 g_wtl2[1024 * 1024];

// ---------------------------------------------------------------------------
__device__ __forceinline__ uint32_t smem_u32(const void* p) {
    uint32_t a;
    asm("{ .reg .u64 t; cvta.to.shared.u64 t, %1; cvt.u32.u64 %0, t; }" : "=r"(a) : "l"(p));
    return a;
}
__device__ __forceinline__ void ldsm_x4(uint32_t r[4], uint32_t addr) {
    asm volatile("ldmatrix.sync.aligned.m8n8.x4.shared.b16 {%0,%1,%2,%3}, [%4];"
                 : "=r"(r[0]), "=r"(r[1]), "=r"(r[2]), "=r"(r[3]) : "r"(addr));
}
__device__ __forceinline__ void mma_bf16(float* c, const uint32_t a[4], const uint32_t* b) {
    asm volatile(
        "mma.sync.aligned.m16n8k16.row.col.f32.bf16.bf16.f32 "
        "{%0,%1,%2,%3}, {%4,%5,%6,%7}, {%8,%9}, {%0,%1,%2,%3};"
        : "+f"(c[0]), "+f"(c[1]), "+f"(c[2]), "+f"(c[3])
        : "r"(a[0]), "r"(a[1]), "r"(a[2]), "r"(a[3]), "r"(b[0]), "r"(b[1]));
}
__device__ __forceinline__ uint32_t pack_bf16x2(__nv_bfloat16 lo, __nv_bfloat16 hi) {
    __nv_bfloat162 p = __halves2bfloat162(lo, hi);
    return *(uint32_t*)&p;
}

// ===========================================================================
// CSR build
// ===========================================================================
__global__ void zero_cnt_kernel(int* c1, int* c2, int n) {
    int i = blockIdx.x * blockDim.x + threadIdx.x;
    if (i < n) { c1[i] = 0; c2[i] = 0; }
}
__global__ void count_kernel(const int* __restrict__ dst1, int E1,
                             const int* __restrict__ dst2, int E2,
                             int* c1, int* c2) {
    int i = blockIdx.x * blockDim.x + threadIdx.x;
    if (i < E1) atomicAdd(&c1[dst1[i]], 1);
    else if (i < E1 + E2) atomicAdd(&c2[dst2[i - E1]], 1);
}

__global__ __launch_bounds__(1024) void scan_kernel(
    const int* c1, int* rp1, int* cur1, float* dinv1,
    const int* c2, int* rp2, int* cur2, float* dinv2, int n) {
    __shared__ int buf[1024];
    __shared__ int carry;
    const int* cnt = blockIdx.x ? c2 : c1;
    int* rp   = blockIdx.x ? rp2   : rp1;
    int* cur  = blockIdx.x ? cur2  : cur1;
    float* dv = blockIdx.x ? dinv2 : dinv1;

    int tid = threadIdx.x;
    if (tid == 0) carry = 0;
    __syncthreads();
    for (int base = 0; base < n; base += 1024) {
        int idx = base + tid;
        int x = (idx < n) ? cnt[idx] : 0;
        buf[tid] = x;
        __syncthreads();
        #pragma unroll
        for (int off = 1; off < 1024; off <<= 1) {
            int v = (tid >= off) ? buf[tid - off] : 0;
            __syncthreads();
            buf[tid] += v;
            __syncthreads();
        }
        int excl = buf[tid] - x;
        int c = carry;
        if (idx < n) {
            rp[idx] = c + excl;
            cur[idx] = c + excl;
            dv[idx] = rsqrtf((float)x + 1.0f);
        }
        __syncthreads();
        if (tid == 0) carry = c + buf[1023];
        __syncthreads();
    }
    if (tid == 0) rp[n] = carry;
}

__global__ void fill_kernel(const int* __restrict__ src1, const int* __restrict__ dst1, int E1,
                            const int* __restrict__ src2, const int* __restrict__ dst2, int E2,
                            int* cur1, int* col1, int* cur2, int* col2) {
    int i = blockIdx.x * blockDim.x + threadIdx.x;
    if (i < E1) {
        int pos = atomicAdd(&cur1[dst1[i]], 1);
        col1[pos] = src1[i];
    } else if (i < E1 + E2) {
        int j = i - E1;
        int pos = atomicAdd(&cur2[dst2[j]], 1);
        col2[pos] = src2[j];
    }
}

// ===========================================================================
// Paired weight transpose-split: W[K,N] -> Th/Tl [N,K] (branch via blockIdx.z)
// ===========================================================================
__global__ __launch_bounds__(1024) void transpose_split2_kernel(
    const float* __restrict__ Wa, __nv_bfloat16* __restrict__ Tha, __nv_bfloat16* __restrict__ Tla,
    const float* __restrict__ Wb, __nv_bfloat16* __restrict__ Thb, __nv_bfloat16* __restrict__ Tlb,
    int K, int N) {
    const float* W = blockIdx.z ? Wb : Wa;
    __nv_bfloat16* Th = blockIdx.z ? Thb : Tha;
    __nv_bfloat16* Tl = blockIdx.z ? Tlb : Tla;
    __shared__ float t[32][33];
    int k = blockIdx.y * 32 + threadIdx.y;
    int n = blockIdx.x * 32 + threadIdx.x;
    t[threadIdx.y][threadIdx.x] = W[(size_t)k * N + n];
    __syncthreads();
    int n2 = blockIdx.x * 32 + threadIdx.y;
    int k2 = blockIdx.y * 32 + threadIdx.x;
    float v = t[threadIdx.x][threadIdx.y];
    __nv_bfloat16 h = __float2bfloat16_rn(v);
    Th[(size_t)n2 * K + k2] = h;
    Tl[(size_t)n2 * K + k2] = __float2bfloat16_rn(v - __bfloat162float(h));
}

// ===========================================================================
// GEMM common constants
// ===========================================================================
#define KC 32
#define LDS 40
#define TILE_B (128 * LDS * 2)
#define BUFSZ  (4 * TILE_B)
#define GEMM_SMEM (2 * BUFSZ)

// ===========================================================================
// GEMM M128: C = (A@W) * (scaleEpi ? dinv[row] : 1); branch via blockIdx.z.
// Natural register allocation; A converted to packed bf16 hi/lo at load.
// ===========================================================================
__global__ __launch_bounds__(256) void gemm_mma_kernel(
    const float* __restrict__ A0, const float* __restrict__ A1,
    const __nv_bfloat16* __restrict__ Bh0, const __nv_bfloat16* __restrict__ Bl0,
    const __nv_bfloat16* __restrict__ Bh1, const __nv_bfloat16* __restrict__ Bl1,
    const float* __restrict__ dinv0, const float* __restrict__ dinv1v,
    float* __restrict__ C0, float* __restrict__ C1,
    int M, int N, int K, int scaleEpi)
{
    extern __shared__ char smem[];

    const int br = blockIdx.z;
    const float* A = br ? A1 : A0;
    const __nv_bfloat16* Bh = br ? Bh1 : Bh0;
    const __nv_bfloat16* Bl = br ? Bl1 : Bl0;
    const float* dinv = br ? dinv1v : dinv0;
    float* C = br ? C1 : C0;

    const int tid = threadIdx.x;
    const int warp = tid >> 5;
    const int lane = tid & 31;
    const int wm = warp & 3;
    const int wn = warp >> 2;
    const int m0 = blockIdx.y * 128;
    const int n0 = blockIdx.x * 128;

    const int lr = tid >> 1;
    const int lh = tid & 1;
    const bool valA = (m0 + lr) < M;

    const int li = lane >> 3;
    const int lrow = lane & 7;
    const int a_mr = ((li & 1) << 3) + lrow;
    const int a_kc = (li >> 1) << 3;
    const int b_nr = ((li >> 1) << 3) + lrow;
    const int b_kc = (li & 1) << 3;

    const uint32_t smem_base = smem_u32(smem);
    const uint32_t offA = ((wm * 32 + a_mr) * LDS + a_kc) * 2;
    const uint32_t offB = ((wn * 64 + b_nr) * LDS + b_kc) * 2;
    const uint32_t stO = (lr * LDS + lh * 16) * 2;

    float acc[2][8][4] = {};

    const float* gA = A + (size_t)(m0 + lr) * K + lh * 16;
    const __nv_bfloat16* gBh = Bh + (size_t)(n0 + lr) * K + lh * 16;
    const __nv_bfloat16* gBl = Bl + (size_t)(n0 + lr) * K + lh * 16;

    uint32_t pAh[8], pAl[8];      // 16 bf16 hi / lo, packed x2
    uint4 rbh[2], rbl[2];

    auto load_g = [&](int kc) {
        if (valA) {
            const float4* p = (const float4*)(gA + kc);
            #pragma unroll
            for (int j = 0; j < 4; j++) {
                float4 v = p[j];
                __nv_bfloat16 h0 = __float2bfloat16_rn(v.x);
                __nv_bfloat16 h1 = __float2bfloat16_rn(v.y);
                __nv_bfloat16 h2 = __float2bfloat16_rn(v.z);
                __nv_bfloat16 h3 = __float2bfloat16_rn(v.w);
                pAh[2 * j]     = pack_bf16x2(h0, h1);
                pAh[2 * j + 1] = pack_bf16x2(h2, h3);
                pAl[2 * j]     = pack_bf16x2(__float2bfloat16_rn(v.x - __bfloat162float(h0)),
                                             __float2bfloat16_rn(v.y - __bfloat162float(h1)));
                pAl[2 * j + 1] = pack_bf16x2(__float2bfloat16_rn(v.z - __bfloat162float(h2)),
                                             __float2bfloat16_rn(v.w - __bfloat162float(h3)));
            }
        } else {
            #pragma unroll
            for (int j = 0; j < 8; j++) { pAh[j] = 0u; pAl[j] = 0u; }
        }
        const uint4* pb = (const uint4*)(gBh + kc);
        rbh[0] = pb[0]; rbh[1] = pb[1];
        pb = (const uint4*)(gBl + kc);
        rbl[0] = pb[0]; rbl[1] = pb[1];
    };

    load_g(0);

    const int nc = K / KC;
    for (int i = 0; i < nc; i++) {
        const uint32_t bb = (i & 1) * BUFSZ;
        char* base = smem + bb;

        // store packed chunk i (no conversion here — done at load)
        {
            uint4* d;
            d = (uint4*)(base + 0 * TILE_B + stO);
            d[0] = make_uint4(pAh[0], pAh[1], pAh[2], pAh[3]);
            d[1] = make_uint4(pAh[4], pAh[5], pAh[6], pAh[7]);
            d = (uint4*)(base + 1 * TILE_B + stO);
            d[0] = make_uint4(pAl[0], pAl[1], pAl[2], pAl[3]);
            d[1] = make_uint4(pAl[4], pAl[5], pAl[6], pAl[7]);
            d = (uint4*)(base + 2 * TILE_B + stO);
            d[0] = rbh[0]; d[1] = rbh[1];
            d = (uint4*)(base + 3 * TILE_B + stO);
            d[0] = rbl[0]; d[1] = rbl[1];
        }

        if (i + 1 < nc) load_g((i + 1) * KC);   // hoisted LDG + convert

        __syncthreads();

        const uint32_t sAh_b = smem_base + bb + 0 * TILE_B;
        const uint32_t sAl_b = smem_base + bb + 1 * TILE_B;
        const uint32_t sBh_b = smem_base + bb + 2 * TILE_B;
        const uint32_t sBl_b = smem_base + bb + 3 * TILE_B;

        #pragma unroll
        for (int ks = 0; ks < 2; ks++) {
            const uint32_t kOff = ks * 16 * 2;
            uint32_t ah[2][4], al[2][4];
            #pragma unroll
            for (int mt = 0; mt < 2; mt++) {
                uint32_t o = offA + kOff + mt * (16 * LDS * 2);
                ldsm_x4(ah[mt], sAh_b + o);
                ldsm_x4(al[mt], sAl_b + o);
            }
            uint32_t bh[4][4], bl[4][4];
            #pragma unroll
            for (int p = 0; p < 4; p++) {
                uint32_t o = offB + kOff + p * (16 * LDS * 2);
                ldsm_x4(bh[p], sBh_b + o);
                ldsm_x4(bl[p], sBl_b + o);
            }
            #pragma unroll
            for (int mt = 0; mt < 2; mt++) {
                #pragma unroll
                for (int p = 0; p < 4; p++) {
                    mma_bf16(acc[mt][2 * p],     ah[mt], &bh[p][0]);
                    mma_bf16(acc[mt][2 * p],     ah[mt], &bl[p][0]);
                    mma_bf16(acc[mt][2 * p],     al[mt], &bh[p][0]);
                    mma_bf16(acc[mt][2 * p + 1], ah[mt], &bh[p][2]);
                    mma_bf16(acc[mt][2 * p + 1], ah[mt], &bl[p][2]);
                    mma_bf16(acc[mt][2 * p + 1], al[mt], &bh[p][2]);
                }
            }
        }
    }

    const int r = lane >> 2;
    const int cq = (lane & 3) * 2;
    #pragma unroll
    for (int mt = 0; mt < 2; mt++) {
        int grow = m0 + wm * 32 + mt * 16 + r;
        float dv0 = 1.f, dv1 = 1.f;
        if (scaleEpi) {
            dv0 = (grow < M)     ? dinv[grow]     : 0.f;
            dv1 = (grow + 8 < M) ? dinv[grow + 8] : 0.f;
        }
        #pragma unroll
        for (int nt = 0; nt < 8; nt++) {
            int gcol = n0 + wn * 64 + nt * 8 + cq;
            if (grow < M)
                *(float2*)&C[(size_t)grow * N + gcol] =
                    make_float2(acc[mt][nt][0] * dv0, acc[mt][nt][1] * dv0);
            if (grow + 8 < M)
                *(float2*)&C[(size_t)(grow + 8) * N + gcol] =
                    make_float2(acc[mt][nt][2] * dv1, acc[mt][nt][3] * dv1);
        }
    }
}

// ===========================================================================
// GEMM M64 variant (for Cout=128) — unchanged from R10
// ===========================================================================
__global__ __launch_bounds__(256) void gemm_mma64_kernel(
    const float* __restrict__ A0, const float* __restrict__ A1,
    const __nv_bfloat16* __restrict__ Bh0, const __nv_bfloat16* __restrict__ Bl0,
    const __nv_bfloat16* __restrict__ Bh1, const __nv_bfloat16* __restrict__ Bl1,
    const float* __restrict__ dinv0, const float* __restrict__ dinv1v,
    float* __restrict__ C0, float* __restrict__ C1,
    int M, int N, int K)
{
    extern __shared__ char smem[];

    const int br = blockIdx.z;
    const float* A = br ? A1 : A0;
    const __nv_bfloat16* Bh = br ? Bh1 : Bh0;
    const __nv_bfloat16* Bl = br ? Bl1 : Bl0;
    const float* dinv = br ? dinv1v : dinv0;
    float* C = br ? C1 : C0;

    const int tid = threadIdx.x;
    const int warp = tid >> 5;
    const int lane = tid & 31;
    const int wm = warp & 1;
    const int wn = warp >> 1;
    const int m0 = blockIdx.y * 64;
    const int n0 = blockIdx.x * 128;

    const int lrA = tid >> 2;
    const int lhA = tid & 3;
    const bool valA = (m0 + lrA) < M;
    const int lrB = tid >> 1;
    const int lhB = tid & 1;

    const int li = lane >> 3;
    const int lrow = lane & 7;
    const int a_mr = ((li & 1) << 3) + lrow;
    const int a_kc = (li >> 1) << 3;
    const int b_nr = ((li >> 1) << 3) + lrow;
    const int b_kc = (li & 1) << 3;

    const uint32_t smem_base = smem_u32(smem);
    const uint32_t offA = ((wm * 32 + a_mr) * LDS + a_kc) * 2;
    const uint32_t offB = ((wn * 32 + b_nr) * LDS + b_kc) * 2;
    const uint32_t stOA = (lrA * LDS + lhA * 8) * 2;
    const uint32_t stOB = (lrB * LDS + lhB * 16) * 2;

    float acc[2][4][4] = {};

    const float* gA = A + (size_t)(m0 + lrA) * K + lhA * 8;
    const __nv_bfloat16* gBh = Bh + (size_t)(n0 + lrB) * K + lhB * 16;
    const __nv_bfloat16* gBl = Bl + (size_t)(n0 + lrB) * K + lhB * 16;

    float fA[8];
    uint4 rbh[2], rbl[2];

    auto load_g = [&](int kc) {
        if (valA) {
            const float4* p = (const float4*)(gA + kc);
            float4 v0 = p[0], v1 = p[1];
            fA[0] = v0.x; fA[1] = v0.y; fA[2] = v0.z; fA[3] = v0.w;
            fA[4] = v1.x; fA[5] = v1.y; fA[6] = v1.z; fA[7] = v1.w;
        } else {
            #pragma unroll
            for (int j = 0; j < 8; j++) fA[j] = 0.f;
        }
        const uint4* pb = (const uint4*)(gBh + kc);
        rbh[0] = pb[0]; rbh[1] = pb[1];
        pb = (const uint4*)(gBl + kc);
        rbl[0] = pb[0]; rbl[1] = pb[1];
    };

    load_g(0);

    const int nc = K / KC;
    for (int i = 0; i < nc; i++) {
        const uint32_t bb = (i & 1) * BUFSZ;
        char* base = smem + bb;

        {
            __nv_bfloat16 hv[8], lv[8];
            #pragma unroll
            for (int j = 0; j < 8; j++) {
                __nv_bfloat16 h = __float2bfloat16_rn(fA[j]);
                hv[j] = h;
                lv[j] = __float2bfloat16_rn(fA[j] - __bfloat162float(h));
            }
            *(uint4*)(base + 0 * TILE_B + stOA) = ((uint4*)hv)[0];
            *(uint4*)(base + 1 * TILE_B + stOA) = ((uint4*)lv)[0];
            uint4* d;
            d = (uint4*)(base + 2 * TILE_B + stOB);
            d[0] = rbh[0]; d[1] = rbh[1];
            d = (uint4*)(base + 3 * TILE_B + stOB);
            d[0] = rbl[0]; d[1] = rbl[1];
        }

        if (i + 1 < nc) load_g((i + 1) * KC);

        __syncthreads();

        const uint32_t sAh_b = smem_base + bb + 0 * TILE_B;
        const uint32_t sAl_b = smem_base + bb + 1 * TILE_B;
        const uint32_t sBh_b = smem_base + bb + 2 * TILE_B;
        const uint32_t sBl_b = smem_base + bb + 3 * TILE_B;

        #pragma unroll
        for (int ks = 0; ks < 2; ks++) {
            const uint32_t kOff = ks * 16 * 2;
            uint32_t ah[2][4], al[2][4];
            #pragma unroll
            for (int mt = 0; mt < 2; mt++) {
                uint32_t o = offA + kOff + mt * (16 * LDS * 2);
                ldsm_x4(ah[mt], sAh_b + o);
                ldsm_x4(al[mt], sAl_b + o);
            }
            uint32_t bh[2][4], bl[2][4];
            #pragma unroll
            for (int p = 0; p < 2; p++) {
                uint32_t o = offB + kOff + p * (16 * LDS * 2);
                ldsm_x4(bh[p], sBh_b + o);
                ldsm_x4(bl[p], sBl_b + o);
            }
            #pragma unroll
            for (int mt = 0; mt < 2; mt++) {
                #pragma unroll
                for (int p = 0; p < 2; p++) {
                    mma_bf16(acc[mt][2 * p],     ah[mt], &bh[p][0]);
                    mma_bf16(acc[mt][2 * p],     ah[mt], &bl[p][0]);
                    mma_bf16(acc[mt][2 * p],     al[mt], &bh[p][0]);
                    mma_bf16(acc[mt][2 * p + 1], ah[mt], &bh[p][2]);
                    mma_bf16(acc[mt][2 * p + 1], ah[mt], &bl[p][2]);
                    mma_bf16(acc[mt][2 * p + 1], al[mt], &bh[p][2]);
                }
            }
        }
    }

    const int r = lane >> 2;
    const int cq = (lane & 3) * 2;
    #pragma unroll
    for (int mt = 0; mt < 2; mt++) {
        int grow = m0 + wm * 32 + mt * 16 + r;
        float dv0 = (grow < M)     ? dinv[grow]     : 0.f;
        float dv1 = (grow + 8 < M) ? dinv[grow + 8] : 0.f;
        #pragma unroll
        for (int nt = 0; nt < 4; nt++) {
            int gcol = n0 + wn * 32 + nt * 8 + cq;
            if (grow < M)
                *(float2*)&C[(size_t)grow * N + gcol] =
                    make_float2(acc[mt][nt][0] * dv0, acc[mt][nt][1] * dv0);
            if (grow + 8 < M)
                *(float2*)&C[(size_t)(grow + 8) * N + gcol] =
                    make_float2(acc[mt][nt][2] * dv1, acc[mt][nt][3] * dv1);
        }
    }
}

// ===========================================================================
// Input-side aggregation (layer 1)
// ===========================================================================
template <int CPL>
__global__ __launch_bounds__(256) void gather_in_kernel(
    const float* __restrict__ x,
    const float* __restrict__ dinv1, const float* __restrict__ dinv2,
    const int* __restrict__ rp1, const int* __restrict__ col1,
    const int* __restrict__ rp2, const int* __restrict__ col2,
    float* __restrict__ y1, float* __restrict__ y2,
    int n, int C, int slices)
{
    const int brn = blockIdx.y;
    const float* dinv = brn ? dinv2 : dinv1;
    const int* rp  = brn ? rp2  : rp1;
    const int* col = brn ? col2 : col1;
    float* y = brn ? y2 : y1;

    int gwarp = (blockIdx.x * blockDim.x + threadIdx.x) >> 5;
    int lane = threadIdx.x & 31;
    int d = gwarp / slices;
    int sl = gwarp - d * slices;
    if (d >= n) return;
    const int f0 = sl * CPL * 32 + lane;

    float dvd = dinv[d];
    float4 acc[CPL];
    {
        const float4* sx = (const float4*)(x + (size_t)d * C);
        #pragma unroll
        for (int j = 0; j < CPL; j++) {
            float4 v = sx[f0 + j * 32];
            acc[j] = make_float4(v.x * dvd, v.y * dvd, v.z * dvd, v.w * dvd);
        }
    }

    int e = rp[d], end = rp[d + 1];
    for (; e + 3 < end; e += 4) {
        int s0 = col[e], s1 = col[e + 1], s2 = col[e + 2], s3 = col[e + 3];
        float c0 = dinv[s0], c1 = dinv[s1], c2 = dinv[s2], c3 = dinv[s3];
        const float4* r0 = (const float4*)(x + (size_t)s0 * C);
        const float4* r1 = (const float4*)(x + (size_t)s1 * C);
        const float4* r2 = (const float4*)(x + (size_t)s2 * C);
        const float4* r3 = (const float4*)(x + (size_t)s3 * C);
        #pragma unroll
        for (int j = 0; j < CPL; j++) {
            float4 v0 = r0[f0 + j * 32];
            float4 v1 = r1[f0 + j * 32];
            float4 v2 = r2[f0 + j * 32];
            float4 v3 = r3[f0 + j * 32];
            acc[j].x += (v0.x * c0 + v1.x * c1) + (v2.x * c2 + v3.x * c3);
            acc[j].y += (v0.y * c0 + v1.y * c1) + (v2.y * c2 + v3.y * c3);
            acc[j].z += (v0.z * c0 + v1.z * c1) + (v2.z * c2 + v3.z * c3);
            acc[j].w += (v0.w * c0 + v1.w * c1) + (v2.w * c2 + v3.w * c3);
        }
    }
    for (; e < end; e++) {
        int s0 = col[e];
        float c0 = dinv[s0];
        const float4* r0 = (const float4*)(x + (size_t)s0 * C);
        #pragma unroll
        for (int j = 0; j < CPL; j++) {
            float4 v = r0[f0 + j * 32];
            acc[j].x += v.x * c0; acc[j].y += v.y * c0;
            acc[j].z += v.z * c0; acc[j].w += v.w * c0;
        }
    }

    float4* o = (float4*)(y + (size_t)d * C);
    #pragma unroll
    for (int j = 0; j < CPL; j++) {
        acc[j].x *= dvd; acc[j].y *= dvd; acc[j].z *= dvd; acc[j].w *= dvd;
        o[f0 + j * 32] = acc[j];
    }
}

// ===========================================================================
// Elementwise combine (layer 1)
// ===========================================================================
__device__ __forceinline__ float elu1(float x) { return x > 0.f ? x : expm1f(x); }

__global__ __launch_bounds__(256) void combine_only_kernel(
    const float* __restrict__ lin1, const float* __restrict__ b1,
    const float* __restrict__ lin2, const float* __restrict__ b2,
    const float* __restrict__ aw,
    float* __restrict__ out, int n, int C)
{
    int idx = blockIdx.x * blockDim.x + threadIdx.x;
    int total = n * (C >> 2);
    if (idx >= total) return;
    int ci = idx % (C >> 2);
    float4 v1 = ((const float4*)lin1)[idx];
    float4 v2 = ((const float4*)lin2)[idx];
    float4 bb1 = ((const float4*)b1)[ci];
    float4 bb2 = ((const float4*)b2)[ci];
    float4 aw0 = ((const float4*)aw)[2 * ci];
    float4 aw1 = ((const float4*)aw)[2 * ci + 1];
    float w0x = 1.0f / (1.0f + expf(aw0.y - aw0.x));
    float w0y = 1.0f / (1.0f + expf(aw0.w - aw0.z));
    float w0z = 1.0f / (1.0f + expf(aw1.y - aw1.x));
    float w0w = 1.0f / (1.0f + expf(aw1.w - aw1.z));
    float4 r;
    r.x = elu1(v1.x + bb1.x) * w0x + elu1(v2.x + bb2.x) * (1.f - w0x);
    r.y = elu1(v1.y + bb1.y) * w0y + elu1(v2.y + bb2.y) * (1.f - w0y);
    r.z = elu1(v1.z + bb1.z) * w0z + elu1(v2.z + bb2.z) * (1.f - w0z);
    r.w = elu1(v1.w + bb1.w) * w0w + elu1(v2.w + bb2.w) * (1.f - w0w);
    ((float4*)out)[idx] = r;
}

// ===========================================================================
// Output-side fused dual gather + bias + ELU + softmax combine (layers 2, 3).
// ===========================================================================
template <int CPL>
__global__ __launch_bounds__(256) void gather_combine_kernel(
    const float* __restrict__ lin1, const float* __restrict__ lin2,
    const float* __restrict__ dinv1, const float* __restrict__ dinv2,
    const int* __restrict__ rp1, const int* __restrict__ col1,
    const int* __restrict__ rp2, const int* __restrict__ col2,
    const float* __restrict__ b1, const float* __restrict__ b2,
    const float* __restrict__ aw,
    float* __restrict__ out, int n, int C, int slices)
{
    int gwarp = (blockIdx.x * blockDim.x + threadIdx.x) >> 5;
    int lane = threadIdx.x & 31;
    int d = gwarp / slices;
    int sl = gwarp - d * slices;
    if (d >= n) return;
    const int f0 = sl * CPL * 32 + lane;

    float4 acc1[CPL], acc2[CPL];
    {
        const float4* s1 = (const float4*)(lin1 + (size_t)d * C);
        const float4* s2 = (const float4*)(lin2 + (size_t)d * C);
        #pragma unroll
        for (int j = 0; j < CPL; j++) { acc1[j] = s1[f0 + j * 32]; acc2[j] = s2[f0 + j * 32]; }
    }

    #pragma unroll
    for (int which = 0; which < 2; which++) {
        const float* lin = which ? lin2 : lin1;
        const int* rp  = which ? rp2  : rp1;
        const int* col = which ? col2 : col1;
        float4* acc = which ? acc2 : acc1;

        int e = rp[d], end = rp[d + 1];
        if (CPL == 1) {
            for (; e + 7 < end; e += 8) {
                #pragma unroll
                for (int q = 0; q < 8; q += 4) {
                    const float4* r0 = (const float4*)(lin + (size_t)col[e + q]     * C);
                    const float4* r1 = (const float4*)(lin + (size_t)col[e + q + 1] * C);
                    const float4* r2 = (const float4*)(lin + (size_t)col[e + q + 2] * C);
                    const float4* r3 = (const float4*)(lin + (size_t)col[e + q + 3] * C);
                    float4 v0 = r0[f0], v1 = r1[f0], v2 = r2[f0], v3 = r3[f0];
                    acc[0].x += (v0.x + v1.x) + (v2.x + v3.x);
                    acc[0].y += (v0.y + v1.y) + (v2.y + v3.y);
                    acc[0].z += (v0.z + v1.z) + (v2.z + v3.z);
                    acc[0].w += (v0.w + v1.w) + (v2.w + v3.w);
                }
            }
        }
        for (; e + 3 < end; e += 4) {
            const float4* r0 = (const float4*)(lin + (size_t)col[e]     * C);
            const float4* r1 = (const float4*)(lin + (size_t)col[e + 1] * C);
            const float4* r2 = (const float4*)(lin + (size_t)col[e + 2] * C);
            const float4* r3 = (const float4*)(lin + (size_t)col[e + 3] * C);
            #pragma unroll
            for (int j = 0; j < CPL; j++) {
                float4 v0 = r0[f0 + j * 32];
                float4 v1 = r1[f0 + j * 32];
                float4 v2 = r2[f0 + j * 32];
                float4 v3 = r3[f0 + j * 32];
                acc[j].x += (v0.x + v1.x) + (v2.x + v3.x);
                acc[j].y += (v0.y + v1.y) + (v2.y + v3.y);
                acc[j].z += (v0.z + v1.z) + (v2.z + v3.z);
                acc[j].w += (v0.w + v1.w) + (v2.w + v3.w);
            }
        }
        for (; e < end; e++) {
            const float4* r0 = (const float4*)(lin + (size_t)col[e] * C);
            #pragma unroll
            for (int j = 0; j < CPL; j++) {
                float4 v = r0[f0 + j * 32];
                acc[j].x += v.x; acc[j].y += v.y; acc[j].z += v.z; acc[j].w += v.w;
            }
        }
    }

    float dv1 = dinv1[d];
    float dv2 = dinv2[d];
    float4* o = (float4*)(out + (size_t)d * C);
    #pragma unroll
    for (int j = 0; j < CPL; j++) {
        int ci = f0 + j * 32;
        float4 bb1 = ((const float4*)b1)[ci];
        float4 bb2 = ((const float4*)b2)[ci];
        float4 aw0 = ((const float4*)aw)[2 * ci];
        float4 aw1 = ((const float4*)aw)[2 * ci + 1];
        float w0x = 1.0f / (1.0f + expf(aw0.y - aw0.x));
        float w0y = 1.0f / (1.0f + expf(aw0.w - aw0.z));
        float w0z = 1.0f / (1.0f + expf(aw1.y - aw1.x));
        float w0w = 1.0f / (1.0f + expf(aw1.w - aw1.z));
        float4 r;
        r.x = elu1(acc1[j].x * dv1 + bb1.x) * w0x + elu1(acc2[j].x * dv2 + bb2.x) * (1.f - w0x);
        r.y = elu1(acc1[j].y * dv1 + bb1.y) * w0y + elu1(acc2[j].y * dv2 + bb2.y) * (1.f - w0y);
        r.z = elu1(acc1[j].z * dv1 + bb1.z) * w0z + elu1(acc2[j].z * dv2 + bb2.z) * (1.f - w0z);
        r.w = elu1(acc1[j].w * dv1 + bb1.w) * w0w + elu1(acc2[j].w * dv2 + bb2.w) * (1.f - w0w);
        o[ci] = r;
    }
}

// ===========================================================================
// Host
// ===========================================================================
extern "C" void kernel_launch(void* const* d_in, const int* in_sizes, int n_in,
                              void* d_out, int out_size)
{
    const float* x   = (const float*)d_in[0];
    const int*   ei1 = (const int*)d_in[1];
    const int*   ei2 = (const int*)d_in[2];
    const float* W11 = (const float*)d_in[3];  const float* b11 = (const float*)d_in[4];
    const float* W12 = (const float*)d_in[5];  const float* b12 = (const float*)d_in[6];
    const float* W21 = (const float*)d_in[7];  const float* b21 = (const float*)d_in[8];
    const float* W22 = (const float*)d_in[9];  const float* b22 = (const float*)d_in[10];
    const float* W31 = (const float*)d_in[11]; const float* b31 = (const float*)d_in[12];
    const float* W32 = (const float*)d_in[13]; const float* b32 = (const float*)d_in[14];
    const float* aw1 = (const float*)d_in[15];
    const float* aw2 = (const float*)d_in[16];
    const float* aw3 = (const float*)d_in[17];

    int n  = in_sizes[0] / 512;
    int E1 = in_sizes[1] / 2;
    int E2 = in_sizes[2] / 2;

    const int* src1 = ei1;
    const int* dst1 = ei1 + E1;
    const int* src2 = ei2;
    const int* dst2 = ei2 + E2;

    float *lin1, *lin2, *h, *y1, *y2, *dinv1, *dinv2;
    int *cnt1, *cnt2, *rp1, *rp2, *cur1, *cur2, *col1, *col2;
    __nv_bfloat16 *wth1, *wtl1, *wth2, *wtl2;
    cudaGetSymbolAddress((void**)&lin1,  g_lin1);
    cudaGetSymbolAddress((void**)&lin2,  g_lin2);
    cudaGetSymbolAddress((void**)&h,     g_h);
    cudaGetSymbolAddress((void**)&y1,    g_y1);
    cudaGetSymbolAddress((void**)&y2,    g_y2);
    cudaGetSymbolAddress((void**)&dinv1, g_dinv1);
    cudaGetSymbolAddress((void**)&dinv2, g_dinv2);
    cudaGetSymbolAddress((void**)&cnt1,  g_cnt1);
    cudaGetSymbolAddress((void**)&cnt2,  g_cnt2);
    cudaGetSymbolAddress((void**)&rp1,   g_rp1);
    cudaGetSymbolAddress((void**)&rp2,   g_rp2);
    cudaGetSymbolAddress((void**)&cur1,  g_cur1);
    cudaGetSymbolAddress((void**)&cur2,  g_cur2);
    cudaGetSymbolAddress((void**)&col1,  g_col1);
    cudaGetSymbolAddress((void**)&col2,  g_col2);
    cudaGetSymbolAddress((void**)&wth1,  g_wth1);
    cudaGetSymbolAddress((void**)&wtl1,  g_wtl1);
    cudaGetSymbolAddress((void**)&wth2,  g_wth2);
    cudaGetSymbolAddress((void**)&wtl2,  g_wtl2);

    cudaFuncSetAttribute(gemm_mma_kernel, cudaFuncAttributeMaxDynamicSharedMemorySize, GEMM_SMEM);
    cudaFuncSetAttribute(gemm_mma64_kernel, cudaFuncAttributeMaxDynamicSharedMemorySize, GEMM_SMEM);

    // CSR build
    zero_cnt_kernel<<<(n + 255) / 256, 256>>>(cnt1, cnt2, n);
    count_kernel<<<(E1 + E2 + 255) / 256, 256>>>(dst1, E1, dst2, E2, cnt1, cnt2);
    scan_kernel<<<2, 1024>>>(cnt1, rp1, cur1, dinv1, cnt2, rp2, cur2, dinv2, n);
    fill_kernel<<<(E1 + E2 + 255) / 256, 256>>>(src1, dst1, E1, src2, dst2, E2,
                                                cur1, col1, cur2, col2);

    dim3 tb(32, 32);

    // ---- Layer 1 (512 -> 1024): aggregate INPUT, GEMM, elementwise combine
    {
        int slices = 2;
        dim3 gi((n * slices * 32 + 255) / 256, 2);
        gather_in_kernel<2><<<gi, 256>>>(x, dinv1, dinv2, rp1, col1, rp2, col2,
                                         y1, y2, n, 512, slices);

        transpose_split2_kernel<<<dim3(1024 / 32, 512 / 32, 2), tb>>>(
            W11, wth1, wtl1, W12, wth2, wtl2, 512, 1024);

        dim3 gg(1024 / 128, (n + 127) / 128, 2);
        gemm_mma_kernel<<<gg, 256, GEMM_SMEM>>>(y1, y2, wth1, wtl1, wth2, wtl2,
                                                dinv1, dinv2, lin1, lin2,
                                                n, 1024, 512, /*scaleEpi=*/0);

        int tot4 = n * (1024 >> 2);
        combine_only_kernel<<<(tot4 + 255) / 256, 256>>>(lin1, b11, lin2, b12, aw1,
                                                         h, n, 1024);
    }

    // ---- Layer 2 (1024 -> 512): GEMM (dinv epi), output gather+combine
    {
        transpose_split2_kernel<<<dim3(512 / 32, 1024 / 32, 2), tb>>>(
            W21, wth1, wtl1, W22, wth2, wtl2, 1024, 512);

        dim3 gg(512 / 128, (n + 127) / 128, 2);
        gemm_mma_kernel<<<gg, 256, GEMM_SMEM>>>(h, h, wth1, wtl1, wth2, wtl2,
                                                dinv1, dinv2, lin1, lin2,
                                                n, 512, 1024, /*scaleEpi=*/1);

        int slices = 2;
        int gblocks = (n * slices * 32 + 255) / 256;
        gather_combine_kernel<2><<<gblocks, 256>>>(lin1, lin2, dinv1, dinv2,
                                                   rp1, col1, rp2, col2,
                                                   b21, b22, aw2, h, n, 512, slices);
    }

    // ---- Layer 3 (512 -> 128): M64 GEMM (dinv epi), output gather+combine
    {
        transpose_split2_kernel<<<dim3(128 / 32, 512 / 32, 2), tb>>>(
            W31, wth1, wtl1, W32, wth2, wtl2, 512, 128);

        dim3 gg(1, (n + 63) / 64, 2);
        gemm_mma64_kernel<<<gg, 256, GEMM_SMEM>>>(h, h, wth1, wtl1, wth2, wtl2,
                                                  dinv1, dinv2, lin1, lin2,
                                                  n, 128, 512);

        int gblocks = (n * 32 + 255) / 256;
        gather_combine_kernel<1><<<gblocks, 256>>>(lin1, lin2, dinv1, dinv2,
                                                   rp1, col1, rp2, col2,
                                                   b31, b32, aw3,
                                                   (float*)d_out, n, 128, 1);
    }
}

// round 16
// speedup vs baseline: 1.2175x; 1.2175x over previous
#include <cuda_runtime.h>
#include <cuda_bf16.h>
#include <cstdint>
#include <math.h>

// ===========================================================================
// GCN2 on GB300: double-buffered mma.sync bf16 3-term-split GEMMs
// + CSR aggregation reordered per layer (layer1 input-side, layer2/3 output).
// R15: full revert to the R10 GEMM (convert at STORE time; prefetch LDGs
// have no consumer until after the MMA block). GEMM is frozen hereafter.
// ===========================================================================

#define NN 10000
#define CMAX 1024
#define EMAX 200000

__device__ float g_lin1[NN * CMAX];
__device__ float g_lin2[NN * CMAX];
__device__ float g_h   [NN * CMAX];
__device__ float g_y1  [NN * 512];
__device__ float g_y2  [NN * 512];
__device__ float g_dinv1[NN];
__device__ float g_dinv2[NN];
__device__ int   g_cnt1[NN];
__device__ int   g_cnt2[NN];
__device__ int   g_rp1[NN + 1];
__device__ int   g_rp2[NN + 1];
__device__ int   g_cur1[NN];
__device__ int   g_cur2[NN];
__device__ int   g_col1[EMAX];
__device__ int   g_col2[EMAX];
__device__ __nv_bfloat16 g_wth1[1024 * 1024];
__device__ __nv_bfloat16 g_wtl1[1024 * 1024];
__device__ __nv_bfloat16 g_wth2[1024 * 1024];
__device__ __nv_bfloat16 g_wtl2[1024 * 1024];

// ---------------------------------------------------------------------------
__device__ __forceinline__ uint32_t smem_u32(const void* p) {
    uint32_t a;
    asm("{ .reg .u64 t; cvta.to.shared.u64 t, %1; cvt.u32.u64 %0, t; }" : "=r"(a) : "l"(p));
    return a;
}
__device__ __forceinline__ void ldsm_x4(uint32_t r[4], uint32_t addr) {
    asm volatile("ldmatrix.sync.aligned.m8n8.x4.shared.b16 {%0,%1,%2,%3}, [%4];"
                 : "=r"(r[0]), "=r"(r[1]), "=r"(r[2]), "=r"(r[3]) : "r"(addr));
}
__device__ __forceinline__ void mma_bf16(float* c, const uint32_t a[4], const uint32_t* b) {
    asm volatile(
        "mma.sync.aligned.m16n8k16.row.col.f32.bf16.bf16.f32 "
        "{%0,%1,%2,%3}, {%4,%5,%6,%7}, {%8,%9}, {%0,%1,%2,%3};"
        : "+f"(c[0]), "+f"(c[1]), "+f"(c[2]), "+f"(c[3])
        : "r"(a[0]), "r"(a[1]), "r"(a[2]), "r"(a[3]), "r"(b[0]), "r"(b[1]));
}

// ===========================================================================
// CSR build
// ===========================================================================
__global__ void count_kernel(const int* __restrict__ dst1, int E1,
                             const int* __restrict__ dst2, int E2,
                             int* c1, int* c2) {
    int i = blockIdx.x * blockDim.x + threadIdx.x;
    if (i < E1) atomicAdd(&c1[dst1[i]], 1);
    else if (i < E1 + E2) atomicAdd(&c2[dst2[i - E1]], 1);
}

__global__ __launch_bounds__(1024) void scan_kernel(
    const int* c1, int* rp1, int* cur1, float* dinv1,
    const int* c2, int* rp2, int* cur2, float* dinv2, int n) {
    __shared__ int buf[1024];
    __shared__ int carry;
    const int* cnt = blockIdx.x ? c2 : c1;
    int* rp   = blockIdx.x ? rp2   : rp1;
    int* cur  = blockIdx.x ? cur2  : cur1;
    float* dv = blockIdx.x ? dinv2 : dinv1;

    int tid = threadIdx.x;
    if (tid == 0) carry = 0;
    __syncthreads();
    for (int base = 0; base < n; base += 1024) {
        int idx = base + tid;
        int x = (idx < n) ? cnt[idx] : 0;
        buf[tid] = x;
        __syncthreads();
        #pragma unroll
        for (int off = 1; off < 1024; off <<= 1) {
            int v = (tid >= off) ? buf[tid - off] : 0;
            __syncthreads();
            buf[tid] += v;
            __syncthreads();
        }
        int excl = buf[tid] - x;
        int c = carry;
        if (idx < n) {
            rp[idx] = c + excl;
            cur[idx] = c + excl;
            dv[idx] = rsqrtf((float)x + 1.0f);
        }
        __syncthreads();
        if (tid == 0) carry = c + buf[1023];
        __syncthreads();
    }
    if (tid == 0) rp[n] = carry;
}

__global__ void fill_kernel(const int* __restrict__ src1, const int* __restrict__ dst1, int E1,
                            const int* __restrict__ src2, const int* __restrict__ dst2, int E2,
                            int* cur1, int* col1, int* cur2, int* col2) {
    int i = blockIdx.x * blockDim.x + threadIdx.x;
    if (i < E1) {
        int pos = atomicAdd(&cur1[dst1[i]], 1);
        col1[pos] = src1[i];
    } else if (i < E1 + E2) {
        int j = i - E1;
        int pos = atomicAdd(&cur2[dst2[j]], 1);
        col2[pos] = src2[j];
    }
}

// ===========================================================================
// Paired weight transpose-split: W[K,N] -> Th/Tl [N,K] (branch via blockIdx.z)
// ===========================================================================
__global__ __launch_bounds__(1024) void transpose_split2_kernel(
    const float* __restrict__ Wa, __nv_bfloat16* __restrict__ Tha, __nv_bfloat16* __restrict__ Tla,
    const float* __restrict__ Wb, __nv_bfloat16* __restrict__ Thb, __nv_bfloat16* __restrict__ Tlb,
    int K, int N) {
    const float* W = blockIdx.z ? Wb : Wa;
    __nv_bfloat16* Th = blockIdx.z ? Thb : Tha;
    __nv_bfloat16* Tl = blockIdx.z ? Tlb : Tla;
    __shared__ float t[32][33];
    int k = blockIdx.y * 32 + threadIdx.y;
    int n = blockIdx.x * 32 + threadIdx.x;
    t[threadIdx.y][threadIdx.x] = W[(size_t)k * N + n];
    __syncthreads();
    int n2 = blockIdx.x * 32 + threadIdx.y;
    int k2 = blockIdx.y * 32 + threadIdx.x;
    float v = t[threadIdx.x][threadIdx.y];
    __nv_bfloat16 h = __float2bfloat16_rn(v);
    Th[(size_t)n2 * K + k2] = h;
    Tl[(size_t)n2 * K + k2] = __float2bfloat16_rn(v - __bfloat162float(h));
}

// ===========================================================================
// GEMM common constants
// ===========================================================================
#define KC 32
#define LDS 40
#define TILE_B (128 * LDS * 2)
#define BUFSZ  (4 * TILE_B)
#define GEMM_SMEM (2 * BUFSZ)

// ===========================================================================
// GEMM M128 (R10 version, FROZEN): C = (A@W) * (scaleEpi ? dinv[row] : 1)
// Prefetch LDGs into fp32/uint4 regs (consumed only at next store);
// fp32->bf16 hi/lo conversion happens at STORE time.
// ===========================================================================
__global__ __launch_bounds__(256) void gemm_mma_kernel(
    const float* __restrict__ A0, const float* __restrict__ A1,
    const __nv_bfloat16* __restrict__ Bh0, const __nv_bfloat16* __restrict__ Bl0,
    const __nv_bfloat16* __restrict__ Bh1, const __nv_bfloat16* __restrict__ Bl1,
    const float* __restrict__ dinv0, const float* __restrict__ dinv1v,
    float* __restrict__ C0, float* __restrict__ C1,
    int M, int N, int K, int scaleEpi)
{
    extern __shared__ char smem[];

    const int br = blockIdx.z;
    const float* A = br ? A1 : A0;
    const __nv_bfloat16* Bh = br ? Bh1 : Bh0;
    const __nv_bfloat16* Bl = br ? Bl1 : Bl0;
    const float* dinv = br ? dinv1v : dinv0;
    float* C = br ? C1 : C0;

    const int tid = threadIdx.x;
    const int warp = tid >> 5;
    const int lane = tid & 31;
    const int wm = warp & 3;
    const int wn = warp >> 2;
    const int m0 = blockIdx.y * 128;
    const int n0 = blockIdx.x * 128;

    const int lr = tid >> 1;
    const int lh = tid & 1;
    const bool valA = (m0 + lr) < M;

    const int li = lane >> 3;
    const int lrow = lane & 7;
    const int a_mr = ((li & 1) << 3) + lrow;
    const int a_kc = (li >> 1) << 3;
    const int b_nr = ((li >> 1) << 3) + lrow;
    const int b_kc = (li & 1) << 3;

    const uint32_t smem_base = smem_u32(smem);
    const uint32_t offA = ((wm * 32 + a_mr) * LDS + a_kc) * 2;
    const uint32_t offB = ((wn * 64 + b_nr) * LDS + b_kc) * 2;
    const uint32_t stO = (lr * LDS + lh * 16) * 2;

    float acc[2][8][4] = {};

    const float* gA = A + (size_t)(m0 + lr) * K + lh * 16;
    const __nv_bfloat16* gBh = Bh + (size_t)(n0 + lr) * K + lh * 16;
    const __nv_bfloat16* gBl = Bl + (size_t)(n0 + lr) * K + lh * 16;

    float fA[16];
    uint4 rbh[2], rbl[2];

    auto load_g = [&](int kc) {
        if (valA) {
            const float4* p = (const float4*)(gA + kc);
            #pragma unroll
            for (int j = 0; j < 4; j++) {
                float4 v = p[j];
                fA[4 * j + 0] = v.x; fA[4 * j + 1] = v.y;
                fA[4 * j + 2] = v.z; fA[4 * j + 3] = v.w;
            }
        } else {
            #pragma unroll
            for (int j = 0; j < 16; j++) fA[j] = 0.f;
        }
        const uint4* pb = (const uint4*)(gBh + kc);
        rbh[0] = pb[0]; rbh[1] = pb[1];
        pb = (const uint4*)(gBl + kc);
        rbl[0] = pb[0]; rbl[1] = pb[1];
    };

    load_g(0);

    const int nc = K / KC;
    for (int i = 0; i < nc; i++) {
        const uint32_t bb = (i & 1) * BUFSZ;
        char* base = smem + bb;

        // convert + store chunk i from regs (first consumption of the prefetch)
        {
            __nv_bfloat16 hv[16], lv[16];
            #pragma unroll
            for (int j = 0; j < 16; j++) {
                __nv_bfloat16 h = __float2bfloat16_rn(fA[j]);
                hv[j] = h;
                lv[j] = __float2bfloat16_rn(fA[j] - __bfloat162float(h));
            }
            uint4* d;
            d = (uint4*)(base + 0 * TILE_B + stO);
            d[0] = ((uint4*)hv)[0]; d[1] = ((uint4*)hv)[1];
            d = (uint4*)(base + 1 * TILE_B + stO);
            d[0] = ((uint4*)lv)[0]; d[1] = ((uint4*)lv)[1];
            d = (uint4*)(base + 2 * TILE_B + stO);
            d[0] = rbh[0]; d[1] = rbh[1];
            d = (uint4*)(base + 3 * TILE_B + stO);
            d[0] = rbl[0]; d[1] = rbl[1];
        }

        if (i + 1 < nc) load_g((i + 1) * KC);   // hoisted LDG (no consumer here)

        __syncthreads();

        const uint32_t sAh_b = smem_base + bb + 0 * TILE_B;
        const uint32_t sAl_b = smem_base + bb + 1 * TILE_B;
        const uint32_t sBh_b = smem_base + bb + 2 * TILE_B;
        const uint32_t sBl_b = smem_base + bb + 3 * TILE_B;

        #pragma unroll
        for (int ks = 0; ks < 2; ks++) {
            const uint32_t kOff = ks * 16 * 2;
            uint32_t ah[2][4], al[2][4];
            #pragma unroll
            for (int mt = 0; mt < 2; mt++) {
                uint32_t o = offA + kOff + mt * (16 * LDS * 2);
                ldsm_x4(ah[mt], sAh_b + o);
                ldsm_x4(al[mt], sAl_b + o);
            }
            uint32_t bh[4][4], bl[4][4];
            #pragma unroll
            for (int p = 0; p < 4; p++) {
                uint32_t o = offB + kOff + p * (16 * LDS * 2);
                ldsm_x4(bh[p], sBh_b + o);
                ldsm_x4(bl[p], sBl_b + o);
            }
            #pragma unroll
            for (int mt = 0; mt < 2; mt++) {
                #pragma unroll
                for (int p = 0; p < 4; p++) {
                    mma_bf16(acc[mt][2 * p],     ah[mt], &bh[p][0]);
                    mma_bf16(acc[mt][2 * p],     ah[mt], &bl[p][0]);
                    mma_bf16(acc[mt][2 * p],     al[mt], &bh[p][0]);
                    mma_bf16(acc[mt][2 * p + 1], ah[mt], &bh[p][2]);
                    mma_bf16(acc[mt][2 * p + 1], ah[mt], &bl[p][2]);
                    mma_bf16(acc[mt][2 * p + 1], al[mt], &bh[p][2]);
                }
            }
        }
    }

    const int r = lane >> 2;
    const int cq = (lane & 3) * 2;
    #pragma unroll
    for (int mt = 0; mt < 2; mt++) {
        int grow = m0 + wm * 32 + mt * 16 + r;
        float dv0 = 1.f, dv1 = 1.f;
        if (scaleEpi) {
            dv0 = (grow < M)     ? dinv[grow]     : 0.f;
            dv1 = (grow + 8 < M) ? dinv[grow + 8] : 0.f;
        }
        #pragma unroll
        for (int nt = 0; nt < 8; nt++) {
            int gcol = n0 + wn * 64 + nt * 8 + cq;
            if (grow < M)
                *(float2*)&C[(size_t)grow * N + gcol] =
                    make_float2(acc[mt][nt][0] * dv0, acc[mt][nt][1] * dv0);
            if (grow + 8 < M)
                *(float2*)&C[(size_t)(grow + 8) * N + gcol] =
                    make_float2(acc[mt][nt][2] * dv1, acc[mt][nt][3] * dv1);
        }
    }
}

// ===========================================================================
// GEMM M64 variant (for Cout=128) — R10 version, frozen
// ===========================================================================
__global__ __launch_bounds__(256) void gemm_mma64_kernel(
    const float* __restrict__ A0, const float* __restrict__ A1,
    const __nv_bfloat16* __restrict__ Bh0, const __nv_bfloat16* __restrict__ Bl0,
    const __nv_bfloat16* __restrict__ Bh1, const __nv_bfloat16* __restrict__ Bl1,
    const float* __restrict__ dinv0, const float* __restrict__ dinv1v,
    float* __restrict__ C0, float* __restrict__ C1,
    int M, int N, int K)
{
    extern __shared__ char smem[];

    const int br = blockIdx.z;
    const float* A = br ? A1 : A0;
    const __nv_bfloat16* Bh = br ? Bh1 : Bh0;
    const __nv_bfloat16* Bl = br ? Bl1 : Bl0;
    const float* dinv = br ? dinv1v : dinv0;
    float* C = br ? C1 : C0;

    const int tid = threadIdx.x;
    const int warp = tid >> 5;
    const int lane = tid & 31;
    const int wm = warp & 1;
    const int wn = warp >> 1;
    const int m0 = blockIdx.y * 64;
    const int n0 = blockIdx.x * 128;

    const int lrA = tid >> 2;
    const int lhA = tid & 3;
    const bool valA = (m0 + lrA) < M;
    const int lrB = tid >> 1;
    const int lhB = tid & 1;

    const int li = lane >> 3;
    const int lrow = lane & 7;
    const int a_mr = ((li & 1) << 3) + lrow;
    const int a_kc = (li >> 1) << 3;
    const int b_nr = ((li >> 1) << 3) + lrow;
    const int b_kc = (li & 1) << 3;

    const uint32_t smem_base = smem_u32(smem);
    const uint32_t offA = ((wm * 32 + a_mr) * LDS + a_kc) * 2;
    const uint32_t offB = ((wn * 32 + b_nr) * LDS + b_kc) * 2;
    const uint32_t stOA = (lrA * LDS + lhA * 8) * 2;
    const uint32_t stOB = (lrB * LDS + lhB * 16) * 2;

    float acc[2][4][4] = {};

    const float* gA = A + (size_t)(m0 + lrA) * K + lhA * 8;
    const __nv_bfloat16* gBh = Bh + (size_t)(n0 + lrB) * K + lhB * 16;
    const __nv_bfloat16* gBl = Bl + (size_t)(n0 + lrB) * K + lhB * 16;

    float fA[8];
    uint4 rbh[2], rbl[2];

    auto load_g = [&](int kc) {
        if (valA) {
            const float4* p = (const float4*)(gA + kc);
            float4 v0 = p[0], v1 = p[1];
            fA[0] = v0.x; fA[1] = v0.y; fA[2] = v0.z; fA[3] = v0.w;
            fA[4] = v1.x; fA[5] = v1.y; fA[6] = v1.z; fA[7] = v1.w;
        } else {
            #pragma unroll
            for (int j = 0; j < 8; j++) fA[j] = 0.f;
        }
        const uint4* pb = (const uint4*)(gBh + kc);
        rbh[0] = pb[0]; rbh[1] = pb[1];
        pb = (const uint4*)(gBl + kc);
        rbl[0] = pb[0]; rbl[1] = pb[1];
    };

    load_g(0);

    const int nc = K / KC;
    for (int i = 0; i < nc; i++) {
        const uint32_t bb = (i & 1) * BUFSZ;
        char* base = smem + bb;

        {
            __nv_bfloat16 hv[8], lv[8];
            #pragma unroll
            for (int j = 0; j < 8; j++) {
                __nv_bfloat16 h = __float2bfloat16_rn(fA[j]);
                hv[j] = h;
                lv[j] = __float2bfloat16_rn(fA[j] - __bfloat162float(h));
            }
            *(uint4*)(base + 0 * TILE_B + stOA) = ((uint4*)hv)[0];
            *(uint4*)(base + 1 * TILE_B + stOA) = ((uint4*)lv)[0];
            uint4* d;
            d = (uint4*)(base + 2 * TILE_B + stOB);
            d[0] = rbh[0]; d[1] = rbh[1];
            d = (uint4*)(base + 3 * TILE_B + stOB);
            d[0] = rbl[0]; d[1] = rbl[1];
        }

        if (i + 1 < nc) load_g((i + 1) * KC);

        __syncthreads();

        const uint32_t sAh_b = smem_base + bb + 0 * TILE_B;
        const uint32_t sAl_b = smem_base + bb + 1 * TILE_B;
        const uint32_t sBh_b = smem_base + bb + 2 * TILE_B;
        const uint32_t sBl_b = smem_base + bb + 3 * TILE_B;

        #pragma unroll
        for (int ks = 0; ks < 2; ks++) {
            const uint32_t kOff = ks * 16 * 2;
            uint32_t ah[2][4], al[2][4];
            #pragma unroll
            for (int mt = 0; mt < 2; mt++) {
                uint32_t o = offA + kOff + mt * (16 * LDS * 2);
                ldsm_x4(ah[mt], sAh_b + o);
                ldsm_x4(al[mt], sAl_b + o);
            }
            uint32_t bh[2][4], bl[2][4];
            #pragma unroll
            for (int p = 0; p < 2; p++) {
                uint32_t o = offB + kOff + p * (16 * LDS * 2);
                ldsm_x4(bh[p], sBh_b + o);
                ldsm_x4(bl[p], sBl_b + o);
            }
            #pragma unroll
            for (int mt = 0; mt < 2; mt++) {
                #pragma unroll
                for (int p = 0; p < 2; p++) {
                    mma_bf16(acc[mt][2 * p],     ah[mt], &bh[p][0]);
                    mma_bf16(acc[mt][2 * p],     ah[mt], &bl[p][0]);
                    mma_bf16(acc[mt][2 * p],     al[mt], &bh[p][0]);
                    mma_bf16(acc[mt][2 * p + 1], ah[mt], &bh[p][2]);
                    mma_bf16(acc[mt][2 * p + 1], ah[mt], &bl[p][2]);
                    mma_bf16(acc[mt][2 * p + 1], al[mt], &bh[p][2]);
                }
            }
        }
    }

    const int r = lane >> 2;
    const int cq = (lane & 3) * 2;
    #pragma unroll
    for (int mt = 0; mt < 2; mt++) {
        int grow = m0 + wm * 32 + mt * 16 + r;
        float dv0 = (grow < M)     ? dinv[grow]     : 0.f;
        float dv1 = (grow + 8 < M) ? dinv[grow + 8] : 0.f;
        #pragma unroll
        for (int nt = 0; nt < 4; nt++) {
            int gcol = n0 + wn * 32 + nt * 8 + cq;
            if (grow < M)
                *(float2*)&C[(size_t)grow * N + gcol] =
                    make_float2(acc[mt][nt][0] * dv0, acc[mt][nt][1] * dv0);
            if (grow + 8 < M)
                *(float2*)&C[(size_t)(grow + 8) * N + gcol] =
                    make_float2(acc[mt][nt][2] * dv1, acc[mt][nt][3] * dv1);
        }
    }
}

// ===========================================================================
// Input-side aggregation (layer 1)
// ===========================================================================
template <int CPL>
__global__ __launch_bounds__(256) void gather_in_kernel(
    const float* __restrict__ x,
    const float* __restrict__ dinv1, const float* __restrict__ dinv2,
    const int* __restrict__ rp1, const int* __restrict__ col1,
    const int* __restrict__ rp2, const int* __restrict__ col2,
    float* __restrict__ y1, float* __restrict__ y2,
    int n, int C, int slices)
{
    const int brn = blockIdx.y;
    const float* dinv = brn ? dinv2 : dinv1;
    const int* rp  = brn ? rp2  : rp1;
    const int* col = brn ? col2 : col1;
    float* y = brn ? y2 : y1;

    int gwarp = (blockIdx.x * blockDim.x + threadIdx.x) >> 5;
    int lane = threadIdx.x & 31;
    int d = gwarp / slices;
    int sl = gwarp - d * slices;
    if (d >= n) return;
    const int f0 = sl * CPL * 32 + lane;

    float dvd = dinv[d];
    float4 acc[CPL];
    {
        const float4* sx = (const float4*)(x + (size_t)d * C);
        #pragma unroll
        for (int j = 0; j < CPL; j++) {
            float4 v = sx[f0 + j * 32];
            acc[j] = make_float4(v.x * dvd, v.y * dvd, v.z * dvd, v.w * dvd);
        }
    }

    int e = rp[d], end = rp[d + 1];
    for (; e + 3 < end; e += 4) {
        int s0 = col[e], s1 = col[e + 1], s2 = col[e + 2], s3 = col[e + 3];
        float c0 = dinv[s0], c1 = dinv[s1], c2 = dinv[s2], c3 = dinv[s3];
        const float4* r0 = (const float4*)(x + (size_t)s0 * C);
        const float4* r1 = (const float4*)(x + (size_t)s1 * C);
        const float4* r2 = (const float4*)(x + (size_t)s2 * C);
        const float4* r3 = (const float4*)(x + (size_t)s3 * C);
        #pragma unroll
        for (int j = 0; j < CPL; j++) {
            float4 v0 = r0[f0 + j * 32];
            float4 v1 = r1[f0 + j * 32];
            float4 v2 = r2[f0 + j * 32];
            float4 v3 = r3[f0 + j * 32];
            acc[j].x += (v0.x * c0 + v1.x * c1) + (v2.x * c2 + v3.x * c3);
            acc[j].y += (v0.y * c0 + v1.y * c1) + (v2.y * c2 + v3.y * c3);
            acc[j].z += (v0.z * c0 + v1.z * c1) + (v2.z * c2 + v3.z * c3);
            acc[j].w += (v0.w * c0 + v1.w * c1) + (v2.w * c2 + v3.w * c3);
        }
    }
    for (; e < end; e++) {
        int s0 = col[e];
        float c0 = dinv[s0];
        const float4* r0 = (const float4*)(x + (size_t)s0 * C);
        #pragma unroll
        for (int j = 0; j < CPL; j++) {
            float4 v = r0[f0 + j * 32];
            acc[j].x += v.x * c0; acc[j].y += v.y * c0;
            acc[j].z += v.z * c0; acc[j].w += v.w * c0;
        }
    }

    float4* o = (float4*)(y + (size_t)d * C);
    #pragma unroll
    for (int j = 0; j < CPL; j++) {
        acc[j].x *= dvd; acc[j].y *= dvd; acc[j].z *= dvd; acc[j].w *= dvd;
        o[f0 + j * 32] = acc[j];
    }
}

// ===========================================================================
// Elementwise combine (layer 1)
// ===========================================================================
__device__ __forceinline__ float elu1(float x) { return x > 0.f ? x : expm1f(x); }

__global__ __launch_bounds__(256) void combine_only_kernel(
    const float* __restrict__ lin1, const float* __restrict__ b1,
    const float* __restrict__ lin2, const float* __restrict__ b2,
    const float* __restrict__ aw,
    float* __restrict__ out, int n, int C)
{
    int idx = blockIdx.x * blockDim.x + threadIdx.x;
    int total = n * (C >> 2);
    if (idx >= total) return;
    int ci = idx % (C >> 2);
    float4 v1 = ((const float4*)lin1)[idx];
    float4 v2 = ((const float4*)lin2)[idx];
    float4 bb1 = ((const float4*)b1)[ci];
    float4 bb2 = ((const float4*)b2)[ci];
    float4 aw0 = ((const float4*)aw)[2 * ci];
    float4 aw1 = ((const float4*)aw)[2 * ci + 1];
    float w0x = 1.0f / (1.0f + expf(aw0.y - aw0.x));
    float w0y = 1.0f / (1.0f + expf(aw0.w - aw0.z));
    float w0z = 1.0f / (1.0f + expf(aw1.y - aw1.x));
    float w0w = 1.0f / (1.0f + expf(aw1.w - aw1.z));
    float4 r;
    r.x = elu1(v1.x + bb1.x) * w0x + elu1(v2.x + bb2.x) * (1.f - w0x);
    r.y = elu1(v1.y + bb1.y) * w0y + elu1(v2.y + bb2.y) * (1.f - w0y);
    r.z = elu1(v1.z + bb1.z) * w0z + elu1(v2.z + bb2.z) * (1.f - w0z);
    r.w = elu1(v1.w + bb1.w) * w0w + elu1(v2.w + bb2.w) * (1.f - w0w);
    ((float4*)out)[idx] = r;
}

// ===========================================================================
// Output-side fused dual gather + bias + ELU + softmax combine (layers 2, 3).
// ===========================================================================
template <int CPL>
__global__ __launch_bounds__(256) void gather_combine_kernel(
    const float* __restrict__ lin1, const float* __restrict__ lin2,
    const float* __restrict__ dinv1, const float* __restrict__ dinv2,
    const int* __restrict__ rp1, const int* __restrict__ col1,
    const int* __restrict__ rp2, const int* __restrict__ col2,
    const float* __restrict__ b1, const float* __restrict__ b2,
    const float* __restrict__ aw,
    float* __restrict__ out, int n, int C, int slices)
{
    int gwarp = (blockIdx.x * blockDim.x + threadIdx.x) >> 5;
    int lane = threadIdx.x & 31;
    int d = gwarp / slices;
    int sl = gwarp - d * slices;
    if (d >= n) return;
    const int f0 = sl * CPL * 32 + lane;

    float4 acc1[CPL], acc2[CPL];
    {
        const float4* s1 = (const float4*)(lin1 + (size_t)d * C);
        const float4* s2 = (const float4*)(lin2 + (size_t)d * C);
        #pragma unroll
        for (int j = 0; j < CPL; j++) { acc1[j] = s1[f0 + j * 32]; acc2[j] = s2[f0 + j * 32]; }
    }

    #pragma unroll
    for (int which = 0; which < 2; which++) {
        const float* lin = which ? lin2 : lin1;
        const int* rp  = which ? rp2  : rp1;
        const int* col = which ? col2 : col1;
        float4* acc = which ? acc2 : acc1;

        int e = rp[d], end = rp[d + 1];
        if (CPL == 1) {
            for (; e + 7 < end; e += 8) {
                #pragma unroll
                for (int q = 0; q < 8; q += 4) {
                    const float4* r0 = (const float4*)(lin + (size_t)col[e + q]     * C);
                    const float4* r1 = (const float4*)(lin + (size_t)col[e + q + 1] * C);
                    const float4* r2 = (const float4*)(lin + (size_t)col[e + q + 2] * C);
                    const float4* r3 = (const float4*)(lin + (size_t)col[e + q + 3] * C);
                    float4 v0 = r0[f0], v1 = r1[f0], v2 = r2[f0], v3 = r3[f0];
                    acc[0].x += (v0.x + v1.x) + (v2.x + v3.x);
                    acc[0].y += (v0.y + v1.y) + (v2.y + v3.y);
                    acc[0].z += (v0.z + v1.z) + (v2.z + v3.z);
                    acc[0].w += (v0.w + v1.w) + (v2.w + v3.w);
                }
            }
        }
        for (; e + 3 < end; e += 4) {
            const float4* r0 = (const float4*)(lin + (size_t)col[e]     * C);
            const float4* r1 = (const float4*)(lin + (size_t)col[e + 1] * C);
            const float4* r2 = (const float4*)(lin + (size_t)col[e + 2] * C);
            const float4* r3 = (const float4*)(lin + (size_t)col[e + 3] * C);
            #pragma unroll
            for (int j = 0; j < CPL; j++) {
                float4 v0 = r0[f0 + j * 32];
                float4 v1 = r1[f0 + j * 32];
                float4 v2 = r2[f0 + j * 32];
                float4 v3 = r3[f0 + j * 32];
                acc[j].x += (v0.x + v1.x) + (v2.x + v3.x);
                acc[j].y += (v0.y + v1.y) + (v2.y + v3.y);
                acc[j].z += (v0.z + v1.z) + (v2.z + v3.z);
                acc[j].w += (v0.w + v1.w) + (v2.w + v3.w);
            }
        }
        for (; e < end; e++) {
            const float4* r0 = (const float4*)(lin + (size_t)col[e] * C);
            #pragma unroll
            for (int j = 0; j < CPL; j++) {
                float4 v = r0[f0 + j * 32];
                acc[j].x += v.x; acc[j].y += v.y; acc[j].z += v.z; acc[j].w += v.w;
            }
        }
    }

    float dv1 = dinv1[d];
    float dv2 = dinv2[d];
    float4* o = (float4*)(out + (size_t)d * C);
    #pragma unroll
    for (int j = 0; j < CPL; j++) {
        int ci = f0 + j * 32;
        float4 bb1 = ((const float4*)b1)[ci];
        float4 bb2 = ((const float4*)b2)[ci];
        float4 aw0 = ((const float4*)aw)[2 * ci];
        float4 aw1 = ((const float4*)aw)[2 * ci + 1];
        float w0x = 1.0f / (1.0f + expf(aw0.y - aw0.x));
        float w0y = 1.0f / (1.0f + expf(aw0.w - aw0.z));
        float w0z = 1.0f / (1.0f + expf(aw1.y - aw1.x));
        float w0w = 1.0f / (1.0f + expf(aw1.w - aw1.z));
        float4 r;
        r.x = elu1(acc1[j].x * dv1 + bb1.x) * w0x + elu1(acc2[j].x * dv2 + bb2.x) * (1.f - w0x);
        r.y = elu1(acc1[j].y * dv1 + bb1.y) * w0y + elu1(acc2[j].y * dv2 + bb2.y) * (1.f - w0y);
        r.z = elu1(acc1[j].z * dv1 + bb1.z) * w0z + elu1(acc2[j].z * dv2 + bb2.z) * (1.f - w0z);
        r.w = elu1(acc1[j].w * dv1 + bb1.w) * w0w + elu1(acc2[j].w * dv2 + bb2.w) * (1.f - w0w);
        o[ci] = r;
    }
}

// ===========================================================================
// Host
// ===========================================================================
extern "C" void kernel_launch(void* const* d_in, const int* in_sizes, int n_in,
                              void* d_out, int out_size)
{
    const float* x   = (const float*)d_in[0];
    const int*   ei1 = (const int*)d_in[1];
    const int*   ei2 = (const int*)d_in[2];
    const float* W11 = (const float*)d_in[3];  const float* b11 = (const float*)d_in[4];
    const float* W12 = (const float*)d_in[5];  const float* b12 = (const float*)d_in[6];
    const float* W21 = (const float*)d_in[7];  const float* b21 = (const float*)d_in[8];
    const float* W22 = (const float*)d_in[9];  const float* b22 = (const float*)d_in[10];
    const float* W31 = (const float*)d_in[11]; const float* b31 = (const float*)d_in[12];
    const float* W32 = (const float*)d_in[13]; const float* b32 = (const float*)d_in[14];
    const float* aw1 = (const float*)d_in[15];
    const float* aw2 = (const float*)d_in[16];
    const float* aw3 = (const float*)d_in[17];

    int n  = in_sizes[0] / 512;
    int E1 = in_sizes[1] / 2;
    int E2 = in_sizes[2] / 2;

    const int* src1 = ei1;
    const int* dst1 = ei1 + E1;
    const int* src2 = ei2;
    const int* dst2 = ei2 + E2;

    float *lin1, *lin2, *h, *y1, *y2, *dinv1, *dinv2;
    int *cnt1, *cnt2, *rp1, *rp2, *cur1, *cur2, *col1, *col2;
    __nv_bfloat16 *wth1, *wtl1, *wth2, *wtl2;
    cudaGetSymbolAddress((void**)&lin1,  g_lin1);
    cudaGetSymbolAddress((void**)&lin2,  g_lin2);
    cudaGetSymbolAddress((void**)&h,     g_h);
    cudaGetSymbolAddress((void**)&y1,    g_y1);
    cudaGetSymbolAddress((void**)&y2,    g_y2);
    cudaGetSymbolAddress((void**)&dinv1, g_dinv1);
    cudaGetSymbolAddress((void**)&dinv2, g_dinv2);
    cudaGetSymbolAddress((void**)&cnt1,  g_cnt1);
    cudaGetSymbolAddress((void**)&cnt2,  g_cnt2);
    cudaGetSymbolAddress((void**)&rp1,   g_rp1);
    cudaGetSymbolAddress((void**)&rp2,   g_rp2);
    cudaGetSymbolAddress((void**)&cur1,  g_cur1);
    cudaGetSymbolAddress((void**)&cur2,  g_cur2);
    cudaGetSymbolAddress((void**)&col1,  g_col1);
    cudaGetSymbolAddress((void**)&col2,  g_col2);
    cudaGetSymbolAddress((void**)&wth1,  g_wth1);
    cudaGetSymbolAddress((void**)&wtl1,  g_wtl1);
    cudaGetSymbolAddress((void**)&wth2,  g_wth2);
    cudaGetSymbolAddress((void**)&wtl2,  g_wtl2);

    cudaFuncSetAttribute(gemm_mma_kernel, cudaFuncAttributeMaxDynamicSharedMemorySize, GEMM_SMEM);
    cudaFuncSetAttribute(gemm_mma64_kernel, cudaFuncAttributeMaxDynamicSharedMemorySize, GEMM_SMEM);

    // CSR build (memset nodes instead of a zero kernel)
    cudaMemsetAsync(cnt1, 0, n * sizeof(int));
    cudaMemsetAsync(cnt2, 0, n * sizeof(int));
    count_kernel<<<(E1 + E2 + 255) / 256, 256>>>(dst1, E1, dst2, E2, cnt1, cnt2);
    scan_kernel<<<2, 1024>>>(cnt1, rp1, cur1, dinv1, cnt2, rp2, cur2, dinv2, n);
    fill_kernel<<<(E1 + E2 + 255) / 256, 256>>>(src1, dst1, E1, src2, dst2, E2,
                                                cur1, col1, cur2, col2);

    dim3 tb(32, 32);

    // ---- Layer 1 (512 -> 1024): aggregate INPUT, GEMM, elementwise combine
    {
        int slices = 2;
        dim3 gi((n * slices * 32 + 255) / 256, 2);
        gather_in_kernel<2><<<gi, 256>>>(x, dinv1, dinv2, rp1, col1, rp2, col2,
                                         y1, y2, n, 512, slices);

        transpose_split2_kernel<<<dim3(1024 / 32, 512 / 32, 2), tb>>>(
            W11, wth1, wtl1, W12, wth2, wtl2, 512, 1024);

        dim3 gg(1024 / 128, (n + 127) / 128, 2);
        gemm_mma_kernel<<<gg, 256, GEMM_SMEM>>>(y1, y2, wth1, wtl1, wth2, wtl2,
                                                dinv1, dinv2, lin1, lin2,
                                                n, 1024, 512, /*scaleEpi=*/0);

        int tot4 = n * (1024 >> 2);
        combine_only_kernel<<<(tot4 + 255) / 256, 256>>>(lin1, b11, lin2, b12, aw1,
                                                         h, n, 1024);
    }

    // ---- Layer 2 (1024 -> 512): GEMM (dinv epi), output gather+combine
    {
        transpose_split2_kernel<<<dim3(512 / 32, 1024 / 32, 2), tb>>>(
            W21, wth1, wtl1, W22, wth2, wtl2, 1024, 512);

        dim3 gg(512 / 128, (n + 127) / 128, 2);
        gemm_mma_kernel<<<gg, 256, GEMM_SMEM>>>(h, h, wth1, wtl1, wth2, wtl2,
                                                dinv1, dinv2, lin1, lin2,
                                                n, 512, 1024, /*scaleEpi=*/1);

        int slices = 2;
        int gblocks = (n * slices * 32 + 255) / 256;
        gather_combine_kernel<2><<<gblocks, 256>>>(lin1, lin2, dinv1, dinv2,
                                                   rp1, col1, rp2, col2,
                                                   b21, b22, aw2, h, n, 512, slices);
    }

    // ---- Layer 3 (512 -> 128): M64 GEMM (dinv epi), output gather+combine
    {
        transpose_split2_kernel<<<dim3(128 / 32, 512 / 32, 2), tb>>>(
            W31, wth1, wtl1, W32, wth2, wtl2, 512, 128);

        dim3 gg(1, (n + 63) / 64, 2);
        gemm_mma64_kernel<<<gg, 256, GEMM_SMEM>>>(h, h, wth1, wtl1, wth2, wtl2,
                                                  dinv1, dinv2, lin1, lin2,
                                                  n, 128, 512);

        int gblocks = (n * 32 + 255) / 256;
        gather_combine_kernel<1><<<gblocks, 256>>>(lin1, lin2, dinv1, dinv2,
                                                   rp1, col1, rp2, col2,
                                                   b31, b32, aw3,
                                                   (float*)d_out, n, 128, 1);
    }
}

// round 17
// speedup vs baseline: 1.2261x; 1.0071x over previous
#include <cuda_runtime.h>
#include <cuda_bf16.h>
#include <cstdint>
#include <math.h>

// ===========================================================================
// GCN2 on GB300: double-buffered mma.sync bf16 3-term-split GEMMs (FROZEN)
// + CSR aggregation reordered per layer (layer1 input-side, layer2/3 output).
// R17: gather parallelism push — slices=4 / CPL=1 / 8-edge unroll on the
// layer-1 input gather and layer-2 output gather (L2 was at 59% of cap).
// ===========================================================================

#define NN 10000
#define CMAX 1024
#define EMAX 200000

__device__ float g_lin1[NN * CMAX];
__device__ float g_lin2[NN * CMAX];
__device__ float g_h   [NN * CMAX];
__device__ float g_y1  [NN * 512];
__device__ float g_y2  [NN * 512];
__device__ float g_dinv1[NN];
__device__ float g_dinv2[NN];
__device__ int   g_cnt1[NN];
__device__ int   g_cnt2[NN];
__device__ int   g_rp1[NN + 1];
__device__ int   g_rp2[NN + 1];
__device__ int   g_cur1[NN];
__device__ int   g_cur2[NN];
__device__ int   g_col1[EMAX];
__device__ int   g_col2[EMAX];
__device__ __nv_bfloat16 g_wth1[1024 * 1024];
__device__ __nv_bfloat16 g_wtl1[1024 * 1024];
__device__ __nv_bfloat16 g_wth2[1024 * 1024];
__device__ __nv_bfloat16 g_wtl2[1024 * 1024];

// ---------------------------------------------------------------------------
__device__ __forceinline__ uint32_t smem_u32(const void* p) {
    uint32_t a;
    asm("{ .reg .u64 t; cvta.to.shared.u64 t, %1; cvt.u32.u64 %0, t; }" : "=r"(a) : "l"(p));
    return a;
}
__device__ __forceinline__ void ldsm_x4(uint32_t r[4], uint32_t addr) {
    asm volatile("ldmatrix.sync.aligned.m8n8.x4.shared.b16 {%0,%1,%2,%3}, [%4];"
                 : "=r"(r[0]), "=r"(r[1]), "=r"(r[2]), "=r"(r[3]) : "r"(addr));
}
__device__ __forceinline__ void mma_bf16(float* c, const uint32_t a[4], const uint32_t* b) {
    asm volatile(
        "mma.sync.aligned.m16n8k16.row.col.f32.bf16.bf16.f32 "
        "{%0,%1,%2,%3}, {%4,%5,%6,%7}, {%8,%9}, {%0,%1,%2,%3};"
        : "+f"(c[0]), "+f"(c[1]), "+f"(c[2]), "+f"(c[3])
        : "r"(a[0]), "r"(a[1]), "r"(a[2]), "r"(a[3]), "r"(b[0]), "r"(b[1]));
}

// ===========================================================================
// CSR build
// ===========================================================================
__global__ void count_kernel(const int* __restrict__ dst1, int E1,
                             const int* __restrict__ dst2, int E2,
                             int* c1, int* c2) {
    int i = blockIdx.x * blockDim.x + threadIdx.x;
    if (i < E1) atomicAdd(&c1[dst1[i]], 1);
    else if (i < E1 + E2) atomicAdd(&c2[dst2[i - E1]], 1);
}

__global__ __launch_bounds__(1024) void scan_kernel(
    const int* c1, int* rp1, int* cur1, float* dinv1,
    const int* c2, int* rp2, int* cur2, float* dinv2, int n) {
    __shared__ int buf[1024];
    __shared__ int carry;
    const int* cnt = blockIdx.x ? c2 : c1;
    int* rp   = blockIdx.x ? rp2   : rp1;
    int* cur  = blockIdx.x ? cur2  : cur1;
    float* dv = blockIdx.x ? dinv2 : dinv1;

    int tid = threadIdx.x;
    if (tid == 0) carry = 0;
    __syncthreads();
    for (int base = 0; base < n; base += 1024) {
        int idx = base + tid;
        int x = (idx < n) ? cnt[idx] : 0;
        buf[tid] = x;
        __syncthreads();
        #pragma unroll
        for (int off = 1; off < 1024; off <<= 1) {
            int v = (tid >= off) ? buf[tid - off] : 0;
            __syncthreads();
            buf[tid] += v;
            __syncthreads();
        }
        int excl = buf[tid] - x;
        int c = carry;
        if (idx < n) {
            rp[idx] = c + excl;
            cur[idx] = c + excl;
            dv[idx] = rsqrtf((float)x + 1.0f);
        }
        __syncthreads();
        if (tid == 0) carry = c + buf[1023];
        __syncthreads();
    }
    if (tid == 0) rp[n] = carry;
}

__global__ void fill_kernel(const int* __restrict__ src1, const int* __restrict__ dst1, int E1,
                            const int* __restrict__ src2, const int* __restrict__ dst2, int E2,
                            int* cur1, int* col1, int* cur2, int* col2) {
    int i = blockIdx.x * blockDim.x + threadIdx.x;
    if (i < E1) {
        int pos = atomicAdd(&cur1[dst1[i]], 1);
        col1[pos] = src1[i];
    } else if (i < E1 + E2) {
        int j = i - E1;
        int pos = atomicAdd(&cur2[dst2[j]], 1);
        col2[pos] = src2[j];
    }
}

// ===========================================================================
// Paired weight transpose-split: W[K,N] -> Th/Tl [N,K] (branch via blockIdx.z)
// ===========================================================================
__global__ __launch_bounds__(1024) void transpose_split2_kernel(
    const float* __restrict__ Wa, __nv_bfloat16* __restrict__ Tha, __nv_bfloat16* __restrict__ Tla,
    const float* __restrict__ Wb, __nv_bfloat16* __restrict__ Thb, __nv_bfloat16* __restrict__ Tlb,
    int K, int N) {
    const float* W = blockIdx.z ? Wb : Wa;
    __nv_bfloat16* Th = blockIdx.z ? Thb : Tha;
    __nv_bfloat16* Tl = blockIdx.z ? Tlb : Tla;
    __shared__ float t[32][33];
    int k = blockIdx.y * 32 + threadIdx.y;
    int n = blockIdx.x * 32 + threadIdx.x;
    t[threadIdx.y][threadIdx.x] = W[(size_t)k * N + n];
    __syncthreads();
    int n2 = blockIdx.x * 32 + threadIdx.y;
    int k2 = blockIdx.y * 32 + threadIdx.x;
    float v = t[threadIdx.x][threadIdx.y];
    __nv_bfloat16 h = __float2bfloat16_rn(v);
    Th[(size_t)n2 * K + k2] = h;
    Tl[(size_t)n2 * K + k2] = __float2bfloat16_rn(v - __bfloat162float(h));
}

// ===========================================================================
// GEMM common constants
// ===========================================================================
#define KC 32
#define LDS 40
#define TILE_B (128 * LDS * 2)
#define BUFSZ  (4 * TILE_B)
#define GEMM_SMEM (2 * BUFSZ)

// ===========================================================================
// GEMM M128 (FROZEN R10 version)
// ===========================================================================
__global__ __launch_bounds__(256) void gemm_mma_kernel(
    const float* __restrict__ A0, const float* __restrict__ A1,
    const __nv_bfloat16* __restrict__ Bh0, const __nv_bfloat16* __restrict__ Bl0,
    const __nv_bfloat16* __restrict__ Bh1, const __nv_bfloat16* __restrict__ Bl1,
    const float* __restrict__ dinv0, const float* __restrict__ dinv1v,
    float* __restrict__ C0, float* __restrict__ C1,
    int M, int N, int K, int scaleEpi)
{
    extern __shared__ char smem[];

    const int br = blockIdx.z;
    const float* A = br ? A1 : A0;
    const __nv_bfloat16* Bh = br ? Bh1 : Bh0;
    const __nv_bfloat16* Bl = br ? Bl1 : Bl0;
    const float* dinv = br ? dinv1v : dinv0;
    float* C = br ? C1 : C0;

    const int tid = threadIdx.x;
    const int warp = tid >> 5;
    const int lane = tid & 31;
    const int wm = warp & 3;
    const int wn = warp >> 2;
    const int m0 = blockIdx.y * 128;
    const int n0 = blockIdx.x * 128;

    const int lr = tid >> 1;
    const int lh = tid & 1;
    const bool valA = (m0 + lr) < M;

    const int li = lane >> 3;
    const int lrow = lane & 7;
    const int a_mr = ((li & 1) << 3) + lrow;
    const int a_kc = (li >> 1) << 3;
    const int b_nr = ((li >> 1) << 3) + lrow;
    const int b_kc = (li & 1) << 3;

    const uint32_t smem_base = smem_u32(smem);
    const uint32_t offA = ((wm * 32 + a_mr) * LDS + a_kc) * 2;
    const uint32_t offB = ((wn * 64 + b_nr) * LDS + b_kc) * 2;
    const uint32_t stO = (lr * LDS + lh * 16) * 2;

    float acc[2][8][4] = {};

    const float* gA = A + (size_t)(m0 + lr) * K + lh * 16;
    const __nv_bfloat16* gBh = Bh + (size_t)(n0 + lr) * K + lh * 16;
    const __nv_bfloat16* gBl = Bl + (size_t)(n0 + lr) * K + lh * 16;

    float fA[16];
    uint4 rbh[2], rbl[2];

    auto load_g = [&](int kc) {
        if (valA) {
            const float4* p = (const float4*)(gA + kc);
            #pragma unroll
            for (int j = 0; j < 4; j++) {
                float4 v = p[j];
                fA[4 * j + 0] = v.x; fA[4 * j + 1] = v.y;
                fA[4 * j + 2] = v.z; fA[4 * j + 3] = v.w;
            }
        } else {
            #pragma unroll
            for (int j = 0; j < 16; j++) fA[j] = 0.f;
        }
        const uint4* pb = (const uint4*)(gBh + kc);
        rbh[0] = pb[0]; rbh[1] = pb[1];
        pb = (const uint4*)(gBl + kc);
        rbl[0] = pb[0]; rbl[1] = pb[1];
    };

    load_g(0);

    const int nc = K / KC;
    for (int i = 0; i < nc; i++) {
        const uint32_t bb = (i & 1) * BUFSZ;
        char* base = smem + bb;

        {
            __nv_bfloat16 hv[16], lv[16];
            #pragma unroll
            for (int j = 0; j < 16; j++) {
                __nv_bfloat16 h = __float2bfloat16_rn(fA[j]);
                hv[j] = h;
                lv[j] = __float2bfloat16_rn(fA[j] - __bfloat162float(h));
            }
            uint4* d;
            d = (uint4*)(base + 0 * TILE_B + stO);
            d[0] = ((uint4*)hv)[0]; d[1] = ((uint4*)hv)[1];
            d = (uint4*)(base + 1 * TILE_B + stO);
            d[0] = ((uint4*)lv)[0]; d[1] = ((uint4*)lv)[1];
            d = (uint4*)(base + 2 * TILE_B + stO);
            d[0] = rbh[0]; d[1] = rbh[1];
            d = (uint4*)(base + 3 * TILE_B + stO);
            d[0] = rbl[0]; d[1] = rbl[1];
        }

        if (i + 1 < nc) load_g((i + 1) * KC);

        __syncthreads();

        const uint32_t sAh_b = smem_base + bb + 0 * TILE_B;
        const uint32_t sAl_b = smem_base + bb + 1 * TILE_B;
        const uint32_t sBh_b = smem_base + bb + 2 * TILE_B;
        const uint32_t sBl_b = smem_base + bb + 3 * TILE_B;

        #pragma unroll
        for (int ks = 0; ks < 2; ks++) {
            const uint32_t kOff = ks * 16 * 2;
            uint32_t ah[2][4], al[2][4];
            #pragma unroll
            for (int mt = 0; mt < 2; mt++) {
                uint32_t o = offA + kOff + mt * (16 * LDS * 2);
                ldsm_x4(ah[mt], sAh_b + o);
                ldsm_x4(al[mt], sAl_b + o);
            }
            uint32_t bh[4][4], bl[4][4];
            #pragma unroll
            for (int p = 0; p < 4; p++) {
                uint32_t o = offB + kOff + p * (16 * LDS * 2);
                ldsm_x4(bh[p], sBh_b + o);
                ldsm_x4(bl[p], sBl_b + o);
            }
            #pragma unroll
            for (int mt = 0; mt < 2; mt++) {
                #pragma unroll
                for (int p = 0; p < 4; p++) {
                    mma_bf16(acc[mt][2 * p],     ah[mt], &bh[p][0]);
                    mma_bf16(acc[mt][2 * p],     ah[mt], &bl[p][0]);
                    mma_bf16(acc[mt][2 * p],     al[mt], &bh[p][0]);
                    mma_bf16(acc[mt][2 * p + 1], ah[mt], &bh[p][2]);
                    mma_bf16(acc[mt][2 * p + 1], ah[mt], &bl[p][2]);
                    mma_bf16(acc[mt][2 * p + 1], al[mt], &bh[p][2]);
                }
            }
        }
    }

    const int r = lane >> 2;
    const int cq = (lane & 3) * 2;
    #pragma unroll
    for (int mt = 0; mt < 2; mt++) {
        int grow = m0 + wm * 32 + mt * 16 + r;
        float dv0 = 1.f, dv1 = 1.f;
        if (scaleEpi) {
            dv0 = (grow < M)     ? dinv[grow]     : 0.f;
            dv1 = (grow + 8 < M) ? dinv[grow + 8] : 0.f;
        }
        #pragma unroll
        for (int nt = 0; nt < 8; nt++) {
            int gcol = n0 + wn * 64 + nt * 8 + cq;
            if (grow < M)
                *(float2*)&C[(size_t)grow * N + gcol] =
                    make_float2(acc[mt][nt][0] * dv0, acc[mt][nt][1] * dv0);
            if (grow + 8 < M)
                *(float2*)&C[(size_t)(grow + 8) * N + gcol] =
                    make_float2(acc[mt][nt][2] * dv1, acc[mt][nt][3] * dv1);
        }
    }
}

// ===========================================================================
// GEMM M64 variant (FROZEN R10 version)
// ===========================================================================
__global__ __launch_bounds__(256) void gemm_mma64_kernel(
    const float* __restrict__ A0, const float* __restrict__ A1,
    const __nv_bfloat16* __restrict__ Bh0, const __nv_bfloat16* __restrict__ Bl0,
    const __nv_bfloat16* __restrict__ Bh1, const __nv_bfloat16* __restrict__ Bl1,
    const float* __restrict__ dinv0, const float* __restrict__ dinv1v,
    float* __restrict__ C0, float* __restrict__ C1,
    int M, int N, int K)
{
    extern __shared__ char smem[];

    const int br = blockIdx.z;
    const float* A = br ? A1 : A0;
    const __nv_bfloat16* Bh = br ? Bh1 : Bh0;
    const __nv_bfloat16* Bl = br ? Bl1 : Bl0;
    const float* dinv = br ? dinv1v : dinv0;
    float* C = br ? C1 : C0;

    const int tid = threadIdx.x;
    const int warp = tid >> 5;
    const int lane = tid & 31;
    const int wm = warp & 1;
    const int wn = warp >> 1;
    const int m0 = blockIdx.y * 64;
    const int n0 = blockIdx.x * 128;

    const int lrA = tid >> 2;
    const int lhA = tid & 3;
    const bool valA = (m0 + lrA) < M;
    const int lrB = tid >> 1;
    const int lhB = tid & 1;

    const int li = lane >> 3;
    const int lrow = lane & 7;
    const int a_mr = ((li & 1) << 3) + lrow;
    const int a_kc = (li >> 1) << 3;
    const int b_nr = ((li >> 1) << 3) + lrow;
    const int b_kc = (li & 1) << 3;

    const uint32_t smem_base = smem_u32(smem);
    const uint32_t offA = ((wm * 32 + a_mr) * LDS + a_kc) * 2;
    const uint32_t offB = ((wn * 32 + b_nr) * LDS + b_kc) * 2;
    const uint32_t stOA = (lrA * LDS + lhA * 8) * 2;
    const uint32_t stOB = (lrB * LDS + lhB * 16) * 2;

    float acc[2][4][4] = {};

    const float* gA = A + (size_t)(m0 + lrA) * K + lhA * 8;
    const __nv_bfloat16* gBh = Bh + (size_t)(n0 + lrB) * K + lhB * 16;
    const __nv_bfloat16* gBl = Bl + (size_t)(n0 + lrB) * K + lhB * 16;

    float fA[8];
    uint4 rbh[2], rbl[2];

    auto load_g = [&](int kc) {
        if (valA) {
            const float4* p = (const float4*)(gA + kc);
            float4 v0 = p[0], v1 = p[1];
            fA[0] = v0.x; fA[1] = v0.y; fA[2] = v0.z; fA[3] = v0.w;
            fA[4] = v1.x; fA[5] = v1.y; fA[6] = v1.z; fA[7] = v1.w;
        } else {
            #pragma unroll
            for (int j = 0; j < 8; j++) fA[j] = 0.f;
        }
        const uint4* pb = (const uint4*)(gBh + kc);
        rbh[0] = pb[0]; rbh[1] = pb[1];
        pb = (const uint4*)(gBl + kc);
        rbl[0] = pb[0]; rbl[1] = pb[1];
    };

    load_g(0);

    const int nc = K / KC;
    for (int i = 0; i < nc; i++) {
        const uint32_t bb = (i & 1) * BUFSZ;
        char* base = smem + bb;

        {
            __nv_bfloat16 hv[8], lv[8];
            #pragma unroll
            for (int j = 0; j < 8; j++) {
                __nv_bfloat16 h = __float2bfloat16_rn(fA[j]);
                hv[j] = h;
                lv[j] = __float2bfloat16_rn(fA[j] - __bfloat162float(h));
            }
            *(uint4*)(base + 0 * TILE_B + stOA) = ((uint4*)hv)[0];
            *(uint4*)(base + 1 * TILE_B + stOA) = ((uint4*)lv)[0];
            uint4* d;
            d = (uint4*)(base + 2 * TILE_B + stOB);
            d[0] = rbh[0]; d[1] = rbh[1];
            d = (uint4*)(base + 3 * TILE_B + stOB);
            d[0] = rbl[0]; d[1] = rbl[1];
        }

        if (i + 1 < nc) load_g((i + 1) * KC);

        __syncthreads();

        const uint32_t sAh_b = smem_base + bb + 0 * TILE_B;
        const uint32_t sAl_b = smem_base + bb + 1 * TILE_B;
        const uint32_t sBh_b = smem_base + bb + 2 * TILE_B;
        const uint32_t sBl_b = smem_base + bb + 3 * TILE_B;

        #pragma unroll
        for (int ks = 0; ks < 2; ks++) {
            const uint32_t kOff = ks * 16 * 2;
            uint32_t ah[2][4], al[2][4];
            #pragma unroll
            for (int mt = 0; mt < 2; mt++) {
                uint32_t o = offA + kOff + mt * (16 * LDS * 2);
                ldsm_x4(ah[mt], sAh_b + o);
                ldsm_x4(al[mt], sAl_b + o);
            }
            uint32_t bh[2][4], bl[2][4];
            #pragma unroll
            for (int p = 0; p < 2; p++) {
                uint32_t o = offB + kOff + p * (16 * LDS * 2);
                ldsm_x4(bh[p], sBh_b + o);
                ldsm_x4(bl[p], sBl_b + o);
            }
            #pragma unroll
            for (int mt = 0; mt < 2; mt++) {
                #pragma unroll
                for (int p = 0; p < 2; p++) {
                    mma_bf16(acc[mt][2 * p],     ah[mt], &bh[p][0]);
                    mma_bf16(acc[mt][2 * p],     ah[mt], &bl[p][0]);
                    mma_bf16(acc[mt][2 * p],     al[mt], &bh[p][0]);
                    mma_bf16(acc[mt][2 * p + 1], ah[mt], &bh[p][2]);
                    mma_bf16(acc[mt][2 * p + 1], ah[mt], &bl[p][2]);
                    mma_bf16(acc[mt][2 * p + 1], al[mt], &bh[p][2]);
                }
            }
        }
    }

    const int r = lane >> 2;
    const int cq = (lane & 3) * 2;
    #pragma unroll
    for (int mt = 0; mt < 2; mt++) {
        int grow = m0 + wm * 32 + mt * 16 + r;
        float dv0 = (grow < M)     ? dinv[grow]     : 0.f;
        float dv1 = (grow + 8 < M) ? dinv[grow + 8] : 0.f;
        #pragma unroll
        for (int nt = 0; nt < 4; nt++) {
            int gcol = n0 + wn * 32 + nt * 8 + cq;
            if (grow < M)
                *(float2*)&C[(size_t)grow * N + gcol] =
                    make_float2(acc[mt][nt][0] * dv0, acc[mt][nt][1] * dv0);
            if (grow + 8 < M)
                *(float2*)&C[(size_t)(grow + 8) * N + gcol] =
                    make_float2(acc[mt][nt][2] * dv1, acc[mt][nt][3] * dv1);
        }
    }
}

// ===========================================================================
// Input-side aggregation (layer 1) — CPL float4/lane; 8-edge unroll at CPL==1
// ===========================================================================
template <int CPL>
__global__ __launch_bounds__(256) void gather_in_kernel(
    const float* __restrict__ x,
    const float* __restrict__ dinv1, const float* __restrict__ dinv2,
    const int* __restrict__ rp1, const int* __restrict__ col1,
    const int* __restrict__ rp2, const int* __restrict__ col2,
    float* __restrict__ y1, float* __restrict__ y2,
    int n, int C, int slices)
{
    const int brn = blockIdx.y;
    const float* dinv = brn ? dinv2 : dinv1;
    const int* rp  = brn ? rp2  : rp1;
    const int* col = brn ? col2 : col1;
    float* y = brn ? y2 : y1;

    int gwarp = (blockIdx.x * blockDim.x + threadIdx.x) >> 5;
    int lane = threadIdx.x & 31;
    int d = gwarp / slices;
    int sl = gwarp - d * slices;
    if (d >= n) return;
    const int f0 = sl * CPL * 32 + lane;

    float dvd = dinv[d];
    float4 acc[CPL];
    {
        const float4* sx = (const float4*)(x + (size_t)d * C);
        #pragma unroll
        for (int j = 0; j < CPL; j++) {
            float4 v = sx[f0 + j * 32];
            acc[j] = make_float4(v.x * dvd, v.y * dvd, v.z * dvd, v.w * dvd);
        }
    }

    int e = rp[d], end = rp[d + 1];
    if (CPL == 1) {
        for (; e + 7 < end; e += 8) {
            int s[8];
            #pragma unroll
            for (int q = 0; q < 8; q++) s[q] = col[e + q];
            float c[8];
            #pragma unroll
            for (int q = 0; q < 8; q++) c[q] = dinv[s[q]];
            float4 v[8];
            #pragma unroll
            for (int q = 0; q < 8; q++)
                v[q] = ((const float4*)(x + (size_t)s[q] * C))[f0];
            #pragma unroll
            for (int q = 0; q < 8; q++) {
                acc[0].x += v[q].x * c[q];
                acc[0].y += v[q].y * c[q];
                acc[0].z += v[q].z * c[q];
                acc[0].w += v[q].w * c[q];
            }
        }
    }
    for (; e + 3 < end; e += 4) {
        int s0 = col[e], s1 = col[e + 1], s2 = col[e + 2], s3 = col[e + 3];
        float c0 = dinv[s0], c1 = dinv[s1], c2 = dinv[s2], c3 = dinv[s3];
        const float4* r0 = (const float4*)(x + (size_t)s0 * C);
        const float4* r1 = (const float4*)(x + (size_t)s1 * C);
        const float4* r2 = (const float4*)(x + (size_t)s2 * C);
        const float4* r3 = (const float4*)(x + (size_t)s3 * C);
        #pragma unroll
        for (int j = 0; j < CPL; j++) {
            float4 v0 = r0[f0 + j * 32];
            float4 v1 = r1[f0 + j * 32];
            float4 v2 = r2[f0 + j * 32];
            float4 v3 = r3[f0 + j * 32];
            acc[j].x += (v0.x * c0 + v1.x * c1) + (v2.x * c2 + v3.x * c3);
            acc[j].y += (v0.y * c0 + v1.y * c1) + (v2.y * c2 + v3.y * c3);
            acc[j].z += (v0.z * c0 + v1.z * c1) + (v2.z * c2 + v3.z * c3);
            acc[j].w += (v0.w * c0 + v1.w * c1) + (v2.w * c2 + v3.w * c3);
        }
    }
    for (; e < end; e++) {
        int s0 = col[e];
        float c0 = dinv[s0];
        const float4* r0 = (const float4*)(x + (size_t)s0 * C);
        #pragma unroll
        for (int j = 0; j < CPL; j++) {
            float4 v = r0[f0 + j * 32];
            acc[j].x += v.x * c0; acc[j].y += v.y * c0;
            acc[j].z += v.z * c0; acc[j].w += v.w * c0;
        }
    }

    float4* o = (float4*)(y + (size_t)d * C);
    #pragma unroll
    for (int j = 0; j < CPL; j++) {
        acc[j].x *= dvd; acc[j].y *= dvd; acc[j].z *= dvd; acc[j].w *= dvd;
        o[f0 + j * 32] = acc[j];
    }
}

// ===========================================================================
// Elementwise combine (layer 1)
// ===========================================================================
__device__ __forceinline__ float elu1(float x) { return x > 0.f ? x : expm1f(x); }

__global__ __launch_bounds__(256) void combine_only_kernel(
    const float* __restrict__ lin1, const float* __restrict__ b1,
    const float* __restrict__ lin2, const float* __restrict__ b2,
    const float* __restrict__ aw,
    float* __restrict__ out, int n, int C)
{
    int idx = blockIdx.x * blockDim.x + threadIdx.x;
    int total = n * (C >> 2);
    if (idx >= total) return;
    int ci = idx % (C >> 2);
    float4 v1 = ((const float4*)lin1)[idx];
    float4 v2 = ((const float4*)lin2)[idx];
    float4 bb1 = ((const float4*)b1)[ci];
    float4 bb2 = ((const float4*)b2)[ci];
    float4 aw0 = ((const float4*)aw)[2 * ci];
    float4 aw1 = ((const float4*)aw)[2 * ci + 1];
    float w0x = 1.0f / (1.0f + expf(aw0.y - aw0.x));
    float w0y = 1.0f / (1.0f + expf(aw0.w - aw0.z));
    float w0z = 1.0f / (1.0f + expf(aw1.y - aw1.x));
    float w0w = 1.0f / (1.0f + expf(aw1.w - aw1.z));
    float4 r;
    r.x = elu1(v1.x + bb1.x) * w0x + elu1(v2.x + bb2.x) * (1.f - w0x);
    r.y = elu1(v1.y + bb1.y) * w0y + elu1(v2.y + bb2.y) * (1.f - w0y);
    r.z = elu1(v1.z + bb1.z) * w0z + elu1(v2.z + bb2.z) * (1.f - w0z);
    r.w = elu1(v1.w + bb1.w) * w0w + elu1(v2.w + bb2.w) * (1.f - w0w);
    ((float4*)out)[idx] = r;
}

// ===========================================================================
// Output-side fused dual gather + bias + ELU + softmax combine (layers 2, 3).
// ===========================================================================
template <int CPL>
__global__ __launch_bounds__(256) void gather_combine_kernel(
    const float* __restrict__ lin1, const float* __restrict__ lin2,
    const float* __restrict__ dinv1, const float* __restrict__ dinv2,
    const int* __restrict__ rp1, const int* __restrict__ col1,
    const int* __restrict__ rp2, const int* __restrict__ col2,
    const float* __restrict__ b1, const float* __restrict__ b2,
    const float* __restrict__ aw,
    float* __restrict__ out, int n, int C, int slices)
{
    int gwarp = (blockIdx.x * blockDim.x + threadIdx.x) >> 5;
    int lane = threadIdx.x & 31;
    int d = gwarp / slices;
    int sl = gwarp - d * slices;
    if (d >= n) return;
    const int f0 = sl * CPL * 32 + lane;

    float4 acc1[CPL], acc2[CPL];
    {
        const float4* s1 = (const float4*)(lin1 + (size_t)d * C);
        const float4* s2 = (const float4*)(lin2 + (size_t)d * C);
        #pragma unroll
        for (int j = 0; j < CPL; j++) { acc1[j] = s1[f0 + j * 32]; acc2[j] = s2[f0 + j * 32]; }
    }

    #pragma unroll
    for (int which = 0; which < 2; which++) {
        const float* lin = which ? lin2 : lin1;
        const int* rp  = which ? rp2  : rp1;
        const int* col = which ? col2 : col1;
        float4* acc = which ? acc2 : acc1;

        int e = rp[d], end = rp[d + 1];
        if (CPL == 1) {
            for (; e + 7 < end; e += 8) {
                int s[8];
                #pragma unroll
                for (int q = 0; q < 8; q++) s[q] = col[e + q];
                float4 v[8];
                #pragma unroll
                for (int q = 0; q < 8; q++)
                    v[q] = ((const float4*)(lin + (size_t)s[q] * C))[f0];
                #pragma unroll
                for (int q = 0; q < 8; q++) {
                    acc[0].x += v[q].x; acc[0].y += v[q].y;
                    acc[0].z += v[q].z; acc[0].w += v[q].w;
                }
            }
        }
        for (; e + 3 < end; e += 4) {
            const float4* r0 = (const float4*)(lin + (size_t)col[e]     * C);
            const float4* r1 = (const float4*)(lin + (size_t)col[e + 1] * C);
            const float4* r2 = (const float4*)(lin + (size_t)col[e + 2] * C);
            const float4* r3 = (const float4*)(lin + (size_t)col[e + 3] * C);
            #pragma unroll
            for (int j = 0; j < CPL; j++) {
                float4 v0 = r0[f0 + j * 32];
                float4 v1 = r1[f0 + j * 32];
                float4 v2 = r2[f0 + j * 32];
                float4 v3 = r3[f0 + j * 32];
                acc[j].x += (v0.x + v1.x) + (v2.x + v3.x);
                acc[j].y += (v0.y + v1.y) + (v2.y + v3.y);
                acc[j].z += (v0.z + v1.z) + (v2.z + v3.z);
                acc[j].w += (v0.w + v1.w) + (v2.w + v3.w);
            }
        }
        for (; e < end; e++) {
            const float4* r0 = (const float4*)(lin + (size_t)col[e] * C);
            #pragma unroll
            for (int j = 0; j < CPL; j++) {
                float4 v = r0[f0 + j * 32];
                acc[j].x += v.x; acc[j].y += v.y; acc[j].z += v.z; acc[j].w += v.w;
            }
        }
    }

    float dv1 = dinv1[d];
    float dv2 = dinv2[d];
    float4* o = (float4*)(out + (size_t)d * C);
    #pragma unroll
    for (int j = 0; j < CPL; j++) {
        int ci = f0 + j * 32;
        float4 bb1 = ((const float4*)b1)[ci];
        float4 bb2 = ((const float4*)b2)[ci];
        float4 aw0 = ((const float4*)aw)[2 * ci];
        float4 aw1 = ((const float4*)aw)[2 * ci + 1];
        float w0x = 1.0f / (1.0f + expf(aw0.y - aw0.x));
        float w0y = 1.0f / (1.0f + expf(aw0.w - aw0.z));
        float w0z = 1.0f / (1.0f + expf(aw1.y - aw1.x));
        float w0w = 1.0f / (1.0f + expf(aw1.w - aw1.z));
        float4 r;
        r.x = elu1(acc1[j].x * dv1 + bb1.x) * w0x + elu1(acc2[j].x * dv2 + bb2.x) * (1.f - w0x);
        r.y = elu1(acc1[j].y * dv1 + bb1.y) * w0y + elu1(acc2[j].y * dv2 + bb2.y) * (1.f - w0y);
        r.z = elu1(acc1[j].z * dv1 + bb1.z) * w0z + elu1(acc2[j].z * dv2 + bb2.z) * (1.f - w0z);
        r.w = elu1(acc1[j].w * dv1 + bb1.w) * w0w + elu1(acc2[j].w * dv2 + bb2.w) * (1.f - w0w);
        o[ci] = r;
    }
}

// ===========================================================================
// Host
// ===========================================================================
extern "C" void kernel_launch(void* const* d_in, const int* in_sizes, int n_in,
                              void* d_out, int out_size)
{
    const float* x   = (const float*)d_in[0];
    const int*   ei1 = (const int*)d_in[1];
    const int*   ei2 = (const int*)d_in[2];
    const float* W11 = (const float*)d_in[3];  const float* b11 = (const float*)d_in[4];
    const float* W12 = (const float*)d_in[5];  const float* b12 = (const float*)d_in[6];
    const float* W21 = (const float*)d_in[7];  const float* b21 = (const float*)d_in[8];
    const float* W22 = (const float*)d_in[9];  const float* b22 = (const float*)d_in[10];
    const float* W31 = (const float*)d_in[11]; const float* b31 = (const float*)d_in[12];
    const float* W32 = (const float*)d_in[13]; const float* b32 = (const float*)d_in[14];
    const float* aw1 = (const float*)d_in[15];
    const float* aw2 = (const float*)d_in[16];
    const float* aw3 = (const float*)d_in[17];

    int n  = in_sizes[0] / 512;
    int E1 = in_sizes[1] / 2;
    int E2 = in_sizes[2] / 2;

    const int* src1 = ei1;
    const int* dst1 = ei1 + E1;
    const int* src2 = ei2;
    const int* dst2 = ei2 + E2;

    float *lin1, *lin2, *h, *y1, *y2, *dinv1, *dinv2;
    int *cnt1, *cnt2, *rp1, *rp2, *cur1, *cur2, *col1, *col2;
    __nv_bfloat16 *wth1, *wtl1, *wth2, *wtl2;
    cudaGetSymbolAddress((void**)&lin1,  g_lin1);
    cudaGetSymbolAddress((void**)&lin2,  g_lin2);
    cudaGetSymbolAddress((void**)&h,     g_h);
    cudaGetSymbolAddress((void**)&y1,    g_y1);
    cudaGetSymbolAddress((void**)&y2,    g_y2);
    cudaGetSymbolAddress((void**)&dinv1, g_dinv1);
    cudaGetSymbolAddress((void**)&dinv2, g_dinv2);
    cudaGetSymbolAddress((void**)&cnt1,  g_cnt1);
    cudaGetSymbolAddress((void**)&cnt2,  g_cnt2);
    cudaGetSymbolAddress((void**)&rp1,   g_rp1);
    cudaGetSymbolAddress((void**)&rp2,   g_rp2);
    cudaGetSymbolAddress((void**)&cur1,  g_cur1);
    cudaGetSymbolAddress((void**)&cur2,  g_cur2);
    cudaGetSymbolAddress((void**)&col1,  g_col1);
    cudaGetSymbolAddress((void**)&col2,  g_col2);
    cudaGetSymbolAddress((void**)&wth1,  g_wth1);
    cudaGetSymbolAddress((void**)&wtl1,  g_wtl1);
    cudaGetSymbolAddress((void**)&wth2,  g_wth2);
    cudaGetSymbolAddress((void**)&wtl2,  g_wtl2);

    cudaFuncSetAttribute(gemm_mma_kernel, cudaFuncAttributeMaxDynamicSharedMemorySize, GEMM_SMEM);
    cudaFuncSetAttribute(gemm_mma64_kernel, cudaFuncAttributeMaxDynamicSharedMemorySize, GEMM_SMEM);

    // CSR build
    cudaMemsetAsync(cnt1, 0, n * sizeof(int));
    cudaMemsetAsync(cnt2, 0, n * sizeof(int));
    count_kernel<<<(E1 + E2 + 255) / 256, 256>>>(dst1, E1, dst2, E2, cnt1, cnt2);
    scan_kernel<<<2, 1024>>>(cnt1, rp1, cur1, dinv1, cnt2, rp2, cur2, dinv2, n);
    fill_kernel<<<(E1 + E2 + 255) / 256, 256>>>(src1, dst1, E1, src2, dst2, E2,
                                                cur1, col1, cur2, col2);

    dim3 tb(32, 32);

    // ---- Layer 1 (512 -> 1024): aggregate INPUT, GEMM, elementwise combine
    {
        int slices = 4;   // CPL=1: 128 ch per warp slice, 8-edge unroll
        dim3 gi((n * slices * 32 + 255) / 256, 2);
        gather_in_kernel<1><<<gi, 256>>>(x, dinv1, dinv2, rp1, col1, rp2, col2,
                                         y1, y2, n, 512, slices);

        transpose_split2_kernel<<<dim3(1024 / 32, 512 / 32, 2), tb>>>(
            W11, wth1, wtl1, W12, wth2, wtl2, 512, 1024);

        dim3 gg(1024 / 128, (n + 127) / 128, 2);
        gemm_mma_kernel<<<gg, 256, GEMM_SMEM>>>(y1, y2, wth1, wtl1, wth2, wtl2,
                                                dinv1, dinv2, lin1, lin2,
                                                n, 1024, 512, /*scaleEpi=*/0);

        int tot4 = n * (1024 >> 2);
        combine_only_kernel<<<(tot4 + 255) / 256, 256>>>(lin1, b11, lin2, b12, aw1,
                                                         h, n, 1024);
    }

    // ---- Layer 2 (1024 -> 512): GEMM (dinv epi), output gather+combine
    {
        transpose_split2_kernel<<<dim3(512 / 32, 1024 / 32, 2), tb>>>(
            W21, wth1, wtl1, W22, wth2, wtl2, 1024, 512);

        dim3 gg(512 / 128, (n + 127) / 128, 2);
        gemm_mma_kernel<<<gg, 256, GEMM_SMEM>>>(h, h, wth1, wtl1, wth2, wtl2,
                                                dinv1, dinv2, lin1, lin2,
                                                n, 512, 1024, /*scaleEpi=*/1);

        int slices = 4;   // CPL=1: 128 ch per warp slice, 8-edge unroll
        int gblocks = (n * slices * 32 + 255) / 256;
        gather_combine_kernel<1><<<gblocks, 256>>>(lin1, lin2, dinv1, dinv2,
                                                   rp1, col1, rp2, col2,
                                                   b21, b22, aw2, h, n, 512, slices);
    }

    // ---- Layer 3 (512 -> 128): M64 GEMM (dinv epi), output gather+combine
    {
        transpose_split2_kernel<<<dim3(128 / 32, 512 / 32, 2), tb>>>(
            W31, wth1, wtl1, W32, wth2, wtl2, 512, 128);

        dim3 gg(1, (n + 63) / 64, 2);
        gemm_mma64_kernel<<<gg, 256, GEMM_SMEM>>>(h, h, wth1, wtl1, wth2, wtl2,
                                                  dinv1, dinv2, lin1, lin2,
                                                  n, 128, 512);

        int gblocks = (n * 32 + 255) / 256;
        gather_combine_kernel<1><<<gblocks, 256>>>(lin1, lin2, dinv1, dinv2,
                                                   rp1, col1, rp2, col2,
                                                   b31, b32, aw3,
                                                   (float*)d_out, n, 128, 1);
    }
}